// round 11
// baseline (speedup 1.0000x reference)
#include <cuda_runtime.h>
#include <cuda_bf16.h>
#include <math.h>

#define N0   120000
#define N1V  12000
#define N2V  1024
#define E1N  300000
#define E2N  10240
#define F_IN 602
#define H1N  8
#define C1N  8
#define D1   64
#define NCLS 41
#define NEG  0.2f

#define EL1  (E1N + N1V)   // 312000
#define EL2  (E2N + N2V)   // 11264
#define KPAD 608
#define CAP  128

// ---------------- scratch ----------------
__device__ float          g_Hfull[(size_t)N0 * D1];
__device__ float          g_as1[N0 * H1N];
__device__ float          g_ad1[N1V * H1N];
__device__ float          g_out1[N1V * D1];
__device__ float          g_H2[N1V * NCLS];
__device__ float          g_as2[N1V];
__device__ float          g_ad2[N2V];
__device__ float          g_s2[N2V];
__device__ float          g_out2[N2V * NCLS];
__device__ __nv_bfloat16  g_W1h[D1 * KPAD];
__device__ __nv_bfloat16  g_W1l[D1 * KPAD];
__device__ int2           g_e2sd[EL2];
__device__ int            g_cnt1[N1V];
__device__ int            g_nbr1[N1V * CAP];

// ================= launch 1: zero =================
__global__ void k_zero() {
    int i = blockIdx.x * blockDim.x + threadIdx.x;
    if (i < N1V) g_cnt1[i] = 0;
    if (i < N2V * NCLS) g_out2[i] = 0.f;
    if (i < N2V) g_s2[i] = 0.f;
}

// ================= launch 2: W1 bf16 hi/lo split =================
__global__ void k_prep_w(const float* __restrict__ W1) {
    int nt = gridDim.x * blockDim.x;
    for (int i = blockIdx.x * blockDim.x + threadIdx.x; i < D1 * KPAD; i += nt) {
        int n = i / KPAD, k = i - n * KPAD;
        float v = (k < F_IN) ? W1[(size_t)k * D1 + n] : 0.f;
        __nv_bfloat16 h = __float2bfloat16(v);
        g_W1h[i] = h;
        g_W1l[i] = __float2bfloat16(v - __bfloat162float(h));
    }
}

// ================= launch 3: edge decode + bucket scatter =================
__global__ void k_prep_e(const void* e1, const void* e2) {
    __shared__ int se64;
    if (threadIdx.x == 0) {
        const long long* p = (const long long*)e1;
        bool ok = true;
        for (int i = 0; i < 16; i++) {
            long long v = p[i];
            if (v < 0 || v >= (long long)N0) { ok = false; break; }
        }
        se64 = ok ? 1 : 0;
    }
    __syncthreads();
    int e64 = se64;
    int nt = gridDim.x * blockDim.x;
    int t0 = blockIdx.x * blockDim.x + threadIdx.x;

    for (int e = t0; e < EL1; e += nt) {
        int s, d;
        if (e < E1N) {
            if (e64) {
                s = (int)((const long long*)e1)[e];
                d = (int)((const long long*)e1)[E1N + e];
            } else {
                s = ((const int*)e1)[e];
                d = ((const int*)e1)[E1N + e];
            }
        } else { s = d = e - E1N; }
        int pos = atomicAdd(&g_cnt1[d], 1);
        if (pos < CAP) g_nbr1[d * CAP + pos] = s;
    }
    for (int e = t0; e < EL2; e += nt) {
        int s, d;
        if (e < E2N) {
            if (e64) {
                s = (int)((const long long*)e2)[e];
                d = (int)((const long long*)e2)[E2N + e];
            } else {
                s = ((const int*)e2)[e];
                d = ((const int*)e2)[E2N + e];
            }
        } else { s = d = e - E2N; }
        g_e2sd[e] = make_int2(s, d);
    }
}

// ================= launch 4: GEMM1 — 512 threads, 16 warps (4Mx4N), 2 CTA/SM =================
#define KC      32
#define NCHUNK  19
#define SA_U32  20
#define SRB     80
#define OFF_AH  0
#define OFF_AL  10240
#define OFF_BH  20480
#define OFF_BL  25600
#define BUFB    30720
#define SMEM_G1 (2 * BUFB)
#define CS_STRIDE 72
#define G1_TPB  512

__device__ __forceinline__ unsigned smem_u32(const void* p) {
    unsigned a;
    asm("{ .reg .u64 t; cvta.to.shared.u64 t, %1; cvt.u32.u64 %0, t; }" : "=r"(a) : "l"(p));
    return a;
}

// packed fp32x2 -> bf16x2 hi/lo split (6 ops / 2 floats)
__device__ __forceinline__ void cvt2(float2 v, unsigned& hp, unsigned& lp) {
    asm("cvt.rn.bf16x2.f32 %0, %1, %2;" : "=r"(hp) : "f"(v.y), "f"(v.x));
    float hx = __uint_as_float(hp << 16);
    float hy = __uint_as_float(hp & 0xffff0000u);
    float lx = v.x - hx, ly = v.y - hy;
    asm("cvt.rn.bf16x2.f32 %0, %1, %2;" : "=r"(lp) : "f"(ly), "f"(lx));
}

__device__ __forceinline__ void mma_bf16(float* c, const unsigned* a, unsigned b0, unsigned b1) {
    asm volatile(
        "mma.sync.aligned.m16n8k16.row.col.f32.bf16.bf16.f32 "
        "{%0,%1,%2,%3}, {%4,%5,%6,%7}, {%8,%9}, {%0,%1,%2,%3};"
        : "+f"(c[0]), "+f"(c[1]), "+f"(c[2]), "+f"(c[3])
        : "r"(a[0]), "r"(a[1]), "r"(a[2]), "r"(a[3]), "r"(b0), "r"(b1));
}

__device__ __forceinline__ void ldm4(unsigned addr, unsigned* r) {
    asm volatile("ldmatrix.sync.aligned.m8n8.x4.shared.b16 {%0,%1,%2,%3}, [%4];"
                 : "=r"(r[0]), "=r"(r[1]), "=r"(r[2]), "=r"(r[3]) : "r"(addr));
}

__device__ __forceinline__ void cpa16(unsigned dst, const void* src) {
    asm volatile("cp.async.cg.shared.global [%0], [%1], 16;" :: "r"(dst), "l"(src));
}

__global__ void __launch_bounds__(G1_TPB, 2)
k_gemm1_mma(const float* __restrict__ x,
            const float* __restrict__ a_src, const float* __restrict__ a_dst) {
    extern __shared__ unsigned char smem[];
    unsigned sb = smem_u32(smem);
    int t = threadIdx.x;
    int w = t >> 5, lane = t & 31;
    int g = lane >> 2, tig = lane & 3;
    int wm = w & 3, wn = w >> 2;           // 4M x 4N warps; warp tile 32M x 16N
    int row0 = blockIdx.x * 128;

    float acc[2][2][4];                    // mi(2 x m16) x ntile(2 x n8) x 4
#pragma unroll
    for (int mi = 0; mi < 2; mi++)
#pragma unroll
        for (int ni = 0; ni < 2; ni++)
#pragma unroll
            for (int q = 0; q < 4; q++) acc[mi][ni][q] = 0.f;

    // B cp.async mapping: threads 0-255 -> hi, 256-511 -> lo
    int tb = t & 255;
    int bn = tb >> 2, bq = tb & 3;
    unsigned b_hl = (t < 256) ? 0u : 5120u;
    unsigned bdst_off = b_hl + (unsigned)(bn * SRB + bq * 16);
    const __nv_bfloat16* bsrc_base = (t < 256) ? g_W1h : g_W1l;
    int bsrc_elem = bn * KPAD + bq * 8;

    // ldmatrix lane offsets
    int arow = ((lane >> 3) & 1) * 8 + (lane & 7);
    unsigned a_loff = (unsigned)((wm * 32 + arow) * SRB + (lane >> 4) * 16);
    int brow = ((lane >> 4) << 3) + (lane & 7);
    unsigned b_loff = (unsigned)((wn * 16 + brow) * SRB + ((lane >> 3) & 1) * 16);

    // -------- prologue: chunk 0 --------
    {
        unsigned* Ah = (unsigned*)(smem + OFF_AH);
        unsigned* Al = (unsigned*)(smem + OFF_AL);
#pragma unroll
        for (int j = 0; j < 4; j++) {
            int idx = t + G1_TPB * j;
            int row = idx >> 4, kq = idx & 15;
            float2 v = make_float2(0.f, 0.f);
            if (row0 + row < N0)
                v = *(const float2*)(x + (size_t)(row0 + row) * F_IN + 2 * kq);
            unsigned hp, lp; cvt2(v, hp, lp);
            Ah[row * SA_U32 + kq] = hp; Al[row * SA_U32 + kq] = lp;
        }
        cpa16(sb + OFF_BH + bdst_off, (const void*)(bsrc_base + bsrc_elem));
        asm volatile("cp.async.commit_group;");
        asm volatile("cp.async.wait_group 0;");
    }
    __syncthreads();

    for (int c = 0; c < NCHUNK; c++) {
        int cur = c & 1, nxt = cur ^ 1;
        bool have_next = (c + 1 < NCHUNK);
        float2 av[4];
        if (have_next) {
            int k0 = (c + 1) * KC;
            cpa16(sb + nxt * BUFB + OFF_BH + bdst_off, (const void*)(bsrc_base + bsrc_elem + k0));
            asm volatile("cp.async.commit_group;");
#pragma unroll
            for (int j = 0; j < 4; j++) {
                int idx = t + G1_TPB * j;
                int row = idx >> 4, kq = idx & 15;
                int gk = k0 + 2 * kq;
                float2 v = make_float2(0.f, 0.f);
                if (row0 + row < N0 && gk < F_IN)
                    v = *(const float2*)(x + (size_t)(row0 + row) * F_IN + gk);
                av[j] = v;
            }
        }
        // -------- compute on current buffer --------
        {
            unsigned abh = sb + cur * BUFB + OFF_AH + a_loff;
            unsigned abl = sb + cur * BUFB + OFF_AL + a_loff;
            unsigned bbh = sb + cur * BUFB + OFF_BH + b_loff;
            unsigned bbl = sb + cur * BUFB + OFF_BL + b_loff;
#pragma unroll
            for (int kb = 0; kb < 2; kb++) {
                unsigned ko = kb * 32;
                unsigned ah[2][4], al[2][4], bv[4];
                // B hi + A hi -> 4 MMAs
                ldm4(bbh + ko, bv);
#pragma unroll
                for (int mi = 0; mi < 2; mi++) {
                    ldm4(abh + mi * (16 * SRB) + ko, ah[mi]);
                    mma_bf16(acc[mi][0], ah[mi], bv[0], bv[1]);
                    mma_bf16(acc[mi][1], ah[mi], bv[2], bv[3]);
                }
                // A lo x B hi -> 4 MMAs
#pragma unroll
                for (int mi = 0; mi < 2; mi++) {
                    ldm4(abl + mi * (16 * SRB) + ko, al[mi]);
                    mma_bf16(acc[mi][0], al[mi], bv[0], bv[1]);
                    mma_bf16(acc[mi][1], al[mi], bv[2], bv[3]);
                }
                // A hi x B lo -> 4 MMAs (reuse bv)
                ldm4(bbl + ko, bv);
#pragma unroll
                for (int mi = 0; mi < 2; mi++) {
                    mma_bf16(acc[mi][0], ah[mi], bv[0], bv[1]);
                    mma_bf16(acc[mi][1], ah[mi], bv[2], bv[3]);
                }
            }
        }
        if (have_next) {
            unsigned* Ah = (unsigned*)(smem + nxt * BUFB + OFF_AH);
            unsigned* Al = (unsigned*)(smem + nxt * BUFB + OFF_AL);
#pragma unroll
            for (int j = 0; j < 4; j++) {
                int idx = t + G1_TPB * j;
                int row = idx >> 4, kq = idx & 15;
                unsigned hp, lp; cvt2(av[j], hp, lp);
                Ah[row * SA_U32 + kq] = hp; Al[row * SA_U32 + kq] = lp;
            }
        }
        asm volatile("cp.async.wait_group 0;");
        __syncthreads();
    }

    // -------- epilogue: stage C in smem, coalesced stores + fused logits --------
    float* Cs = (float*)smem;
#pragma unroll
    for (int mi = 0; mi < 2; mi++)
#pragma unroll
        for (int ni = 0; ni < 2; ni++) {
            int r = wm * 32 + mi * 16 + g;
            int cc = wn * 16 + ni * 8 + tig * 2;
            Cs[r * CS_STRIDE + cc]           = acc[mi][ni][0];
            Cs[r * CS_STRIDE + cc + 1]       = acc[mi][ni][1];
            Cs[(r + 8) * CS_STRIDE + cc]     = acc[mi][ni][2];
            Cs[(r + 8) * CS_STRIDE + cc + 1] = acc[mi][ni][3];
        }
    __syncthreads();

#pragma unroll
    for (int it = 0; it < 4; it++) {
        int r = (t >> 4) + 32 * it;
        int c4 = (t & 15) * 4;
        if (row0 + r < N0) {
            float4 v = *(const float4*)(Cs + r * CS_STRIDE + c4);
            *(float4*)(g_Hfull + (size_t)(row0 + r) * D1 + c4) = v;
        }
    }
    if (t < 128) {
        int m = row0 + t;
        if (m < N0) {
            const float* rr = Cs + t * CS_STRIDE;
#pragma unroll
            for (int h = 0; h < H1N; h++) {
                float as = 0.f, ad = 0.f;
#pragma unroll
                for (int cc = 0; cc < C1N; cc++) {
                    float v = rr[h * C1N + cc];
                    as = fmaf(v, __ldg(&a_src[h * C1N + cc]), as);
                    ad = fmaf(v, __ldg(&a_dst[h * C1N + cc]), ad);
                }
                g_as1[m * H1N + h] = as;
                if (m < N1V) g_ad1[m * H1N + h] = ad;
            }
        }
    }
}

// ================= launch 5: fused layer-1 softmax + aggregate =================
#define EXS 9
__global__ void __launch_bounds__(256)
k_edge1_fused(const float* __restrict__ b1) {
    __shared__ float s_ex[8][CAP * EXS];
    __shared__ int   s_nbr[8][CAP];
    int wid = threadIdx.x >> 5, lane = threadIdx.x & 31;
    int node = blockIdx.x * 8 + wid;
    if (node >= N1V) return;
    int deg = g_cnt1[node];
    if (deg > CAP) deg = CAP;
    float* exs = s_ex[wid];
    int* nbs = s_nbr[wid];

    float4 adA = __ldg((const float4*)&g_ad1[node * 8]);
    float4 adB = __ldg((const float4*)&g_ad1[node * 8 + 4]);
    float sum[8] = {0.f, 0.f, 0.f, 0.f, 0.f, 0.f, 0.f, 0.f};

    for (int e = lane; e < deg; e += 32) {
        int s = __ldg(&g_nbr1[node * CAP + e]);
        nbs[e] = s;
        float4 sa = __ldg((const float4*)&g_as1[s * 8]);
        float4 sbv = __ldg((const float4*)&g_as1[s * 8 + 4]);
        float a[8] = { sa.x + adA.x, sa.y + adA.y, sa.z + adA.z, sa.w + adA.w,
                       sbv.x + adB.x, sbv.y + adB.y, sbv.z + adB.z, sbv.w + adB.w };
#pragma unroll
        for (int h = 0; h < 8; h++) {
            float v = a[h] > 0.f ? a[h] : NEG * a[h];
            float ex = expf(v);
            sum[h] += ex;
            exs[e * EXS + h] = ex;
        }
    }
    __syncwarp();
#pragma unroll
    for (int h = 0; h < 8; h++)
#pragma unroll
        for (int o = 16; o > 0; o >>= 1)
            sum[h] += __shfl_xor_sync(0xffffffffu, sum[h], o);

    int myh = lane >> 2;
    float myr = 1.f / (sum[myh] + 1e-16f);

    float ax = 0.f, ay = 0.f;
#pragma unroll 4
    for (int e = 0; e < deg; e++) {
        float wgt = exs[e * EXS + myh] * myr;
        int s = nbs[e];
        float2 hv = __ldg((const float2*)&g_Hfull[(size_t)s * D1 + 2 * lane]);
        ax = fmaf(wgt, hv.x, ax);
        ay = fmaf(wgt, hv.y, ay);
    }
    float bx = __ldg(&b1[2 * lane]), by = __ldg(&b1[2 * lane + 1]);
    float vx = ax + bx; vx = vx > 0.f ? vx : expm1f(vx);
    float vy = ay + by; vy = vy > 0.f ? vy : expm1f(vy);
    *(float2*)&g_out1[node * D1 + 2 * lane] = make_float2(vx, vy);
}

// ================= layer 2 =================
__global__ void k_gemm2(const float* __restrict__ W2) {
    __shared__ float Ws[D1 * NCLS];
    for (int i = threadIdx.x; i < D1 * NCLS; i += blockDim.x) Ws[i] = W2[i];
    __syncthreads();
    int t = blockIdx.x * blockDim.x + threadIdx.x;
    if (t >= N1V * NCLS) return;
    int row = t / NCLS, col = t - row * NCLS;
    const float* hr = g_out1 + row * D1;
    float acc = 0.f;
#pragma unroll
    for (int k = 0; k < D1; k++) acc = fmaf(hr[k], Ws[k * NCLS + col], acc);
    g_H2[t] = acc;
}

__global__ void k_att2(const float* __restrict__ a_src, const float* __restrict__ a_dst) {
    int i = blockIdx.x * blockDim.x + threadIdx.x;
    if (i >= N1V) return;
    const float* hp = g_H2 + i * NCLS;
    float as = 0.f;
#pragma unroll
    for (int c = 0; c < NCLS; c++) as += hp[c] * a_src[c];
    g_as2[i] = as;
    if (i < N2V) {
        float ad = 0.f;
#pragma unroll
        for (int c = 0; c < NCLS; c++) ad += hp[c] * a_dst[c];
        g_ad2[i] = ad;
    }
}

__global__ void k_edge2_sum() {
    int e = blockIdx.x * blockDim.x + threadIdx.x;
    if (e >= EL2) return;
    int2 sd = g_e2sd[e];
    float al = g_as2[sd.x] + g_ad2[sd.y];
    al = al > 0.f ? al : NEG * al;
    atomicAdd(&g_s2[sd.y], expf(al));
}

__global__ void k_edge2_agg() {
    int t = blockIdx.x * blockDim.x + threadIdx.x;
    if (t >= EL2 * NCLS) return;
    int e = t / NCLS, c = t - e * NCLS;
    int2 sd = g_e2sd[e];
    float al = g_as2[sd.x] + g_ad2[sd.y];
    al = al > 0.f ? al : NEG * al;
    float w = expf(al) / (g_s2[sd.y] + 1e-16f);
    atomicAdd(&g_out2[sd.y * NCLS + c], g_H2[sd.x * NCLS + c] * w);
}

__global__ void k_final(float* __restrict__ out, const float* __restrict__ b2) {
    int d = blockIdx.x;
    int lane = threadIdx.x;
    float v0 = (lane < NCLS) ? g_out2[d * NCLS + lane] + b2[lane] : -INFINITY;
    float v1 = (lane + 32 < NCLS) ? g_out2[d * NCLS + lane + 32] + b2[lane + 32] : -INFINITY;
    float m = fmaxf(v0, v1);
#pragma unroll
    for (int o = 16; o > 0; o >>= 1) m = fmaxf(m, __shfl_xor_sync(0xffffffffu, m, o));
    float s = ((lane < NCLS) ? expf(v0 - m) : 0.f) + ((lane + 32 < NCLS) ? expf(v1 - m) : 0.f);
#pragma unroll
    for (int o = 16; o > 0; o >>= 1) s += __shfl_xor_sync(0xffffffffu, s, o);
    float ls = m + logf(s);
    if (lane < NCLS) out[d * NCLS + lane] = v0 - ls;
    if (lane + 32 < NCLS) out[d * NCLS + lane + 32] = v1 - ls;
}

// ---------------- launch ----------------
extern "C" void kernel_launch(void* const* d_in, const int* in_sizes, int n_in,
                              void* d_out, int out_size) {
    const float* x = nullptr;
    const void* e1 = nullptr;
    const void* e2 = nullptr;
    const float *W1 = nullptr, *as1 = nullptr, *ad1 = nullptr, *b1 = nullptr;
    const float *W2 = nullptr, *as2 = nullptr, *ad2 = nullptr, *b2 = nullptr;

    for (int i = 0; i < n_in; i++) {
        switch (in_sizes[i]) {
            case N0 * F_IN:   x  = (const float*)d_in[i]; break;
            case 2 * E1N:     e1 = d_in[i]; break;
            case 2 * E2N:     e2 = d_in[i]; break;
            case F_IN * D1:
                W1  = (const float*)d_in[i];
                if (i + 3 < n_in) {
                    as1 = (const float*)d_in[i + 1];
                    ad1 = (const float*)d_in[i + 2];
                    b1  = (const float*)d_in[i + 3];
                }
                break;
            case D1 * NCLS:
                W2  = (const float*)d_in[i];
                if (i + 3 < n_in) {
                    as2 = (const float*)d_in[i + 1];
                    ad2 = (const float*)d_in[i + 2];
                    b2  = (const float*)d_in[i + 3];
                }
                break;
            default: break;
        }
    }

    float* out = (float*)d_out;
    const int TPB = 256;

    cudaFuncSetAttribute(k_gemm1_mma, cudaFuncAttributeMaxDynamicSharedMemorySize, SMEM_G1);

    k_zero<<<(N2V * NCLS + TPB - 1) / TPB, TPB>>>();                 // 1
    k_prep_w<<<160, TPB>>>(W1);                                       // 2
    k_prep_e<<<512, TPB>>>(e1, e2);                                   // 3
    k_gemm1_mma<<<(N0 + 127) / 128, G1_TPB, SMEM_G1>>>(x, as1, ad1);  // 4 <- profiled
    k_edge1_fused<<<(N1V + 7) / 8, TPB>>>(b1);                        // 5
    k_gemm2<<<(N1V * NCLS + TPB - 1) / TPB, TPB>>>(W2);               // 6
    k_att2<<<(N1V + TPB - 1) / TPB, TPB>>>(as2, ad2);                 // 7
    k_edge2_sum<<<(EL2 + TPB - 1) / TPB, TPB>>>();                    // 8
    k_edge2_agg<<<(EL2 * NCLS + TPB - 1) / TPB, TPB>>>();             // 9
    k_final<<<N2V, 32>>>(out, b2);                                    // 10
}

// round 12
// speedup vs baseline: 1.1254x; 1.1254x over previous
#include <cuda_runtime.h>
#include <cuda_bf16.h>
#include <cuda_fp16.h>
#include <math.h>

#define N0   120000
#define N1V  12000
#define N2V  1024
#define E1N  300000
#define E2N  10240
#define F_IN 602
#define H1N  8
#define C1N  8
#define D1   64
#define NCLS 41
#define NEG  0.2f

#define EL1  (E1N + N1V)   // 312000
#define EL2  (E2N + N2V)   // 11264
#define KPAD 608
#define CAP  128

// ---------------- scratch ----------------
__device__ float          g_Hfull[(size_t)N0 * D1];
__device__ float          g_as1[N0 * H1N];
__device__ float          g_ad1[N1V * H1N];
__device__ float          g_out1[N1V * D1];
__device__ float          g_H2[N1V * NCLS];
__device__ float          g_as2[N1V];
__device__ float          g_ad2[N2V];
__device__ float          g_s2[N2V];
__device__ float          g_out2[N2V * NCLS];
__device__ __half         g_W1h[D1 * KPAD];   // fp16(W1), [n][kpad]
__device__ int2           g_e2sd[EL2];
__device__ int            g_cnt1[N1V];
__device__ int            g_nbr1[N1V * CAP];

// ================= launch 1: zero =================
__global__ void k_zero() {
    int i = blockIdx.x * blockDim.x + threadIdx.x;
    if (i < N1V) g_cnt1[i] = 0;
    if (i < N2V * NCLS) g_out2[i] = 0.f;
    if (i < N2V) g_s2[i] = 0.f;
}

// ================= launch 2: W1 fp16 =================
__global__ void k_prep_w(const float* __restrict__ W1) {
    int nt = gridDim.x * blockDim.x;
    for (int i = blockIdx.x * blockDim.x + threadIdx.x; i < D1 * KPAD; i += nt) {
        int n = i / KPAD, k = i - n * KPAD;
        float v = (k < F_IN) ? W1[(size_t)k * D1 + n] : 0.f;
        g_W1h[i] = __float2half_rn(v);
    }
}

// ================= launch 3: edge decode + bucket scatter =================
__global__ void k_prep_e(const void* e1, const void* e2) {
    __shared__ int se64;
    if (threadIdx.x == 0) {
        const long long* p = (const long long*)e1;
        bool ok = true;
        for (int i = 0; i < 16; i++) {
            long long v = p[i];
            if (v < 0 || v >= (long long)N0) { ok = false; break; }
        }
        se64 = ok ? 1 : 0;
    }
    __syncthreads();
    int e64 = se64;
    int nt = gridDim.x * blockDim.x;
    int t0 = blockIdx.x * blockDim.x + threadIdx.x;

    for (int e = t0; e < EL1; e += nt) {
        int s, d;
        if (e < E1N) {
            if (e64) {
                s = (int)((const long long*)e1)[e];
                d = (int)((const long long*)e1)[E1N + e];
            } else {
                s = ((const int*)e1)[e];
                d = ((const int*)e1)[E1N + e];
            }
        } else { s = d = e - E1N; }
        int pos = atomicAdd(&g_cnt1[d], 1);
        if (pos < CAP) g_nbr1[d * CAP + pos] = s;
    }
    for (int e = t0; e < EL2; e += nt) {
        int s, d;
        if (e < E2N) {
            if (e64) {
                s = (int)((const long long*)e2)[e];
                d = (int)((const long long*)e2)[E2N + e];
            } else {
                s = ((const int*)e2)[e];
                d = ((const int*)e2)[E2N + e];
            }
        } else { s = d = e - E2N; }
        g_e2sd[e] = make_int2(s, d);
    }
}

// ================= launch 4: GEMM1 — fp16x2 split, 256 thr, 8 warps (4Mx2N) =================
#define KC      32
#define NCHUNK  19
#define SA_U32  20
#define SRB     80
#define OFF_AH  0
#define OFF_AL  10240
#define OFF_BH  20480
#define BUFB    25600
#define SMEM_G1 (2 * BUFB)   // 51200
#define CS_STRIDE 72

__device__ __forceinline__ unsigned smem_u32(const void* p) {
    unsigned a;
    asm("{ .reg .u64 t; cvta.to.shared.u64 t, %1; cvt.u32.u64 %0, t; }" : "=r"(a) : "l"(p));
    return a;
}

// fp32x2 -> f16x2 hi + f16x2 lo (residual)
__device__ __forceinline__ void cvt2h(float2 v, unsigned& hp, unsigned& lp) {
    __half2 h = __float22half2_rn(v);
    float2 hf = __half22float2(h);
    __half2 l = __float22half2_rn(make_float2(v.x - hf.x, v.y - hf.y));
    hp = *(unsigned*)&h;
    lp = *(unsigned*)&l;
}

__device__ __forceinline__ void mma_f16(float* c, const unsigned* a, unsigned b0, unsigned b1) {
    asm volatile(
        "mma.sync.aligned.m16n8k16.row.col.f32.f16.f16.f32 "
        "{%0,%1,%2,%3}, {%4,%5,%6,%7}, {%8,%9}, {%0,%1,%2,%3};"
        : "+f"(c[0]), "+f"(c[1]), "+f"(c[2]), "+f"(c[3])
        : "r"(a[0]), "r"(a[1]), "r"(a[2]), "r"(a[3]), "r"(b0), "r"(b1));
}

__device__ __forceinline__ void ldm4(unsigned addr, unsigned* r) {
    asm volatile("ldmatrix.sync.aligned.m8n8.x4.shared.b16 {%0,%1,%2,%3}, [%4];"
                 : "=r"(r[0]), "=r"(r[1]), "=r"(r[2]), "=r"(r[3]) : "r"(addr));
}

__device__ __forceinline__ void cpa16(unsigned dst, const void* src) {
    asm volatile("cp.async.cg.shared.global [%0], [%1], 16;" :: "r"(dst), "l"(src));
}

__global__ void __launch_bounds__(256, 2)
k_gemm1_mma(const float* __restrict__ x,
            const float* __restrict__ a_src, const float* __restrict__ a_dst) {
    extern __shared__ unsigned char smem[];
    unsigned sb = smem_u32(smem);
    int t = threadIdx.x;
    int w = t >> 5, lane = t & 31;
    int g = lane >> 2, tig = lane & 3;
    int wm = w & 3, wn = w >> 2;     // 4M x 2N warps, warp tile 32x32
    int row0 = blockIdx.x * 128;

    float acc[2][4][4];
#pragma unroll
    for (int mi = 0; mi < 2; mi++)
#pragma unroll
        for (int ni = 0; ni < 4; ni++)
#pragma unroll
            for (int q = 0; q < 4; q++) acc[mi][ni][q] = 0.f;

    // B cp.async: 64 rows x 64B = 256 16B ops, one per thread
    int bn = t >> 2, bq = t & 3;
    unsigned bdst_off = (unsigned)(bn * SRB + bq * 16);
    int bsrc_elem = bn * KPAD + bq * 8;

    int arow = ((lane >> 3) & 1) * 8 + (lane & 7);
    unsigned a_loff = (unsigned)((wm * 32 + arow) * SRB + (lane >> 4) * 16);
    int brow = ((lane >> 4) << 3) + (lane & 7);
    unsigned b_loff = (unsigned)((wn * 32 + brow) * SRB + ((lane >> 3) & 1) * 16);

    // -------- prologue: chunk 0 --------
    {
        unsigned* Ah = (unsigned*)(smem + OFF_AH);
        unsigned* Al = (unsigned*)(smem + OFF_AL);
#pragma unroll
        for (int j = 0; j < 8; j++) {
            int idx = t + 256 * j;
            int row = idx >> 4, kq = idx & 15;
            float2 v = make_float2(0.f, 0.f);
            if (row0 + row < N0)
                v = *(const float2*)(x + (size_t)(row0 + row) * F_IN + 2 * kq);
            unsigned hp, lp; cvt2h(v, hp, lp);
            Ah[row * SA_U32 + kq] = hp; Al[row * SA_U32 + kq] = lp;
        }
        cpa16(sb + OFF_BH + bdst_off, (const void*)(g_W1h + bsrc_elem));
        asm volatile("cp.async.commit_group;");
        asm volatile("cp.async.wait_group 0;");
    }
    __syncthreads();

    for (int c = 0; c < NCHUNK; c++) {
        int cur = c & 1, nxt = cur ^ 1;
        bool have_next = (c + 1 < NCHUNK);
        float2 av[8];
        if (have_next) {
            int k0 = (c + 1) * KC;
            cpa16(sb + nxt * BUFB + OFF_BH + bdst_off, (const void*)(g_W1h + bsrc_elem + k0));
            asm volatile("cp.async.commit_group;");
#pragma unroll
            for (int j = 0; j < 8; j++) {
                int idx = t + 256 * j;
                int row = idx >> 4, kq = idx & 15;
                int gk = k0 + 2 * kq;
                float2 v = make_float2(0.f, 0.f);
                if (row0 + row < N0 && gk < F_IN)
                    v = *(const float2*)(x + (size_t)(row0 + row) * F_IN + gk);
                av[j] = v;
            }
        }
        // -------- compute on current buffer: (Ah + Al) x Bh --------
        {
            unsigned abh = sb + cur * BUFB + OFF_AH + a_loff;
            unsigned abl = sb + cur * BUFB + OFF_AL + a_loff;
            unsigned bbh = sb + cur * BUFB + OFF_BH + b_loff;
#pragma unroll
            for (int kb = 0; kb < 2; kb++) {
                unsigned ko = kb * 32;
                unsigned ah[2][4], al[2][4], bh[2][4];
#pragma unroll
                for (int mi = 0; mi < 2; mi++) {
                    ldm4(abh + mi * (16 * SRB) + ko, ah[mi]);
                    ldm4(abl + mi * (16 * SRB) + ko, al[mi]);
                }
#pragma unroll
                for (int nb = 0; nb < 2; nb++)
                    ldm4(bbh + nb * (16 * SRB) + ko, bh[nb]);
#pragma unroll
                for (int mi = 0; mi < 2; mi++)
#pragma unroll
                    for (int nb = 0; nb < 2; nb++) {
                        mma_f16(acc[mi][nb * 2 + 0], ah[mi], bh[nb][0], bh[nb][1]);
                        mma_f16(acc[mi][nb * 2 + 1], ah[mi], bh[nb][2], bh[nb][3]);
                        mma_f16(acc[mi][nb * 2 + 0], al[mi], bh[nb][0], bh[nb][1]);
                        mma_f16(acc[mi][nb * 2 + 1], al[mi], bh[nb][2], bh[nb][3]);
                    }
            }
        }
        if (have_next) {
            unsigned* Ah = (unsigned*)(smem + nxt * BUFB + OFF_AH);
            unsigned* Al = (unsigned*)(smem + nxt * BUFB + OFF_AL);
#pragma unroll
            for (int j = 0; j < 8; j++) {
                int idx = t + 256 * j;
                int row = idx >> 4, kq = idx & 15;
                unsigned hp, lp; cvt2h(av[j], hp, lp);
                Ah[row * SA_U32 + kq] = hp; Al[row * SA_U32 + kq] = lp;
            }
        }
        asm volatile("cp.async.wait_group 0;");
        __syncthreads();
    }

    // -------- epilogue --------
    float* Cs = (float*)smem;
#pragma unroll
    for (int mi = 0; mi < 2; mi++)
#pragma unroll
        for (int ni = 0; ni < 4; ni++) {
            int r = wm * 32 + mi * 16 + g;
            int cc = wn * 32 + ni * 8 + tig * 2;
            Cs[r * CS_STRIDE + cc]           = acc[mi][ni][0];
            Cs[r * CS_STRIDE + cc + 1]       = acc[mi][ni][1];
            Cs[(r + 8) * CS_STRIDE + cc]     = acc[mi][ni][2];
            Cs[(r + 8) * CS_STRIDE + cc + 1] = acc[mi][ni][3];
        }
    __syncthreads();

#pragma unroll
    for (int it = 0; it < 8; it++) {
        int r = (t >> 4) + 16 * it;
        int c4 = (t & 15) * 4;
        if (row0 + r < N0) {
            float4 v = *(const float4*)(Cs + r * CS_STRIDE + c4);
            *(float4*)(g_Hfull + (size_t)(row0 + r) * D1 + c4) = v;
        }
    }
    if (t < 128) {
        int m = row0 + t;
        if (m < N0) {
            const float* rr = Cs + t * CS_STRIDE;
#pragma unroll
            for (int h = 0; h < H1N; h++) {
                float as = 0.f, ad = 0.f;
#pragma unroll
                for (int cc = 0; cc < C1N; cc++) {
                    float v = rr[h * C1N + cc];
                    as = fmaf(v, __ldg(&a_src[h * C1N + cc]), as);
                    ad = fmaf(v, __ldg(&a_dst[h * C1N + cc]), ad);
                }
                g_as1[m * H1N + h] = as;
                if (m < N1V) g_ad1[m * H1N + h] = ad;
            }
        }
    }
}

// ================= launch 5: fused layer-1 softmax + aggregate =================
#define EXS 9
__global__ void __launch_bounds__(256)
k_edge1_fused(const float* __restrict__ b1) {
    __shared__ float s_ex[8][CAP * EXS];
    __shared__ int   s_nbr[8][CAP];
    int wid = threadIdx.x >> 5, lane = threadIdx.x & 31;
    int node = blockIdx.x * 8 + wid;
    if (node >= N1V) return;
    int deg = g_cnt1[node];
    if (deg > CAP) deg = CAP;
    float* exs = s_ex[wid];
    int* nbs = s_nbr[wid];

    float4 adA = __ldg((const float4*)&g_ad1[node * 8]);
    float4 adB = __ldg((const float4*)&g_ad1[node * 8 + 4]);
    float sum[8] = {0.f, 0.f, 0.f, 0.f, 0.f, 0.f, 0.f, 0.f};

    for (int e = lane; e < deg; e += 32) {
        int s = __ldg(&g_nbr1[node * CAP + e]);
        nbs[e] = s;
        float4 sa = __ldg((const float4*)&g_as1[s * 8]);
        float4 sbv = __ldg((const float4*)&g_as1[s * 8 + 4]);
        float a[8] = { sa.x + adA.x, sa.y + adA.y, sa.z + adA.z, sa.w + adA.w,
                       sbv.x + adB.x, sbv.y + adB.y, sbv.z + adB.z, sbv.w + adB.w };
#pragma unroll
        for (int h = 0; h < 8; h++) {
            float v = a[h] > 0.f ? a[h] : NEG * a[h];
            float ex = expf(v);
            sum[h] += ex;
            exs[e * EXS + h] = ex;
        }
    }
    __syncwarp();
#pragma unroll
    for (int h = 0; h < 8; h++)
#pragma unroll
        for (int o = 16; o > 0; o >>= 1)
            sum[h] += __shfl_xor_sync(0xffffffffu, sum[h], o);

    int myh = lane >> 2;
    float myr = 1.f / (sum[myh] + 1e-16f);

    float ax = 0.f, ay = 0.f;
#pragma unroll 4
    for (int e = 0; e < deg; e++) {
        float wgt = exs[e * EXS + myh] * myr;
        int s = nbs[e];
        float2 hv = __ldg((const float2*)&g_Hfull[(size_t)s * D1 + 2 * lane]);
        ax = fmaf(wgt, hv.x, ax);
        ay = fmaf(wgt, hv.y, ay);
    }
    float bx = __ldg(&b1[2 * lane]), by = __ldg(&b1[2 * lane + 1]);
    float vx = ax + bx; vx = vx > 0.f ? vx : expm1f(vx);
    float vy = ay + by; vy = vy > 0.f ? vy : expm1f(vy);
    *(float2*)&g_out1[node * D1 + 2 * lane] = make_float2(vx, vy);
}

// ================= layer 2 =================
__global__ void k_gemm2(const float* __restrict__ W2) {
    __shared__ float Ws[D1 * NCLS];
    for (int i = threadIdx.x; i < D1 * NCLS; i += blockDim.x) Ws[i] = W2[i];
    __syncthreads();
    int t = blockIdx.x * blockDim.x + threadIdx.x;
    if (t >= N1V * NCLS) return;
    int row = t / NCLS, col = t - row * NCLS;
    const float* hr = g_out1 + row * D1;
    float acc = 0.f;
#pragma unroll
    for (int k = 0; k < D1; k++) acc = fmaf(hr[k], Ws[k * NCLS + col], acc);
    g_H2[t] = acc;
}

__global__ void k_att2(const float* __restrict__ a_src, const float* __restrict__ a_dst) {
    int i = blockIdx.x * blockDim.x + threadIdx.x;
    if (i >= N1V) return;
    const float* hp = g_H2 + i * NCLS;
    float as = 0.f;
#pragma unroll
    for (int c = 0; c < NCLS; c++) as += hp[c] * a_src[c];
    g_as2[i] = as;
    if (i < N2V) {
        float ad = 0.f;
#pragma unroll
        for (int c = 0; c < NCLS; c++) ad += hp[c] * a_dst[c];
        g_ad2[i] = ad;
    }
}

__global__ void k_edge2_sum() {
    int e = blockIdx.x * blockDim.x + threadIdx.x;
    if (e >= EL2) return;
    int2 sd = g_e2sd[e];
    float al = g_as2[sd.x] + g_ad2[sd.y];
    al = al > 0.f ? al : NEG * al;
    atomicAdd(&g_s2[sd.y], expf(al));
}

__global__ void k_edge2_agg() {
    int t = blockIdx.x * blockDim.x + threadIdx.x;
    if (t >= EL2 * NCLS) return;
    int e = t / NCLS, c = t - e * NCLS;
    int2 sd = g_e2sd[e];
    float al = g_as2[sd.x] + g_ad2[sd.y];
    al = al > 0.f ? al : NEG * al;
    float w = expf(al) / (g_s2[sd.y] + 1e-16f);
    atomicAdd(&g_out2[sd.y * NCLS + c], g_H2[sd.x * NCLS + c] * w);
}

__global__ void k_final(float* __restrict__ out, const float* __restrict__ b2) {
    int d = blockIdx.x;
    int lane = threadIdx.x;
    float v0 = (lane < NCLS) ? g_out2[d * NCLS + lane] + b2[lane] : -INFINITY;
    float v1 = (lane + 32 < NCLS) ? g_out2[d * NCLS + lane + 32] + b2[lane + 32] : -INFINITY;
    float m = fmaxf(v0, v1);
#pragma unroll
    for (int o = 16; o > 0; o >>= 1) m = fmaxf(m, __shfl_xor_sync(0xffffffffu, m, o));
    float s = ((lane < NCLS) ? expf(v0 - m) : 0.f) + ((lane + 32 < NCLS) ? expf(v1 - m) : 0.f);
#pragma unroll
    for (int o = 16; o > 0; o >>= 1) s += __shfl_xor_sync(0xffffffffu, s, o);
    float ls = m + logf(s);
    if (lane < NCLS) out[d * NCLS + lane] = v0 - ls;
    if (lane + 32 < NCLS) out[d * NCLS + lane + 32] = v1 - ls;
}

// ---------------- launch ----------------
extern "C" void kernel_launch(void* const* d_in, const int* in_sizes, int n_in,
                              void* d_out, int out_size) {
    const float* x = nullptr;
    const void* e1 = nullptr;
    const void* e2 = nullptr;
    const float *W1 = nullptr, *as1 = nullptr, *ad1 = nullptr, *b1 = nullptr;
    const float *W2 = nullptr, *as2 = nullptr, *ad2 = nullptr, *b2 = nullptr;

    for (int i = 0; i < n_in; i++) {
        switch (in_sizes[i]) {
            case N0 * F_IN:   x  = (const float*)d_in[i]; break;
            case 2 * E1N:     e1 = d_in[i]; break;
            case 2 * E2N:     e2 = d_in[i]; break;
            case F_IN * D1:
                W1  = (const float*)d_in[i];
                if (i + 3 < n_in) {
                    as1 = (const float*)d_in[i + 1];
                    ad1 = (const float*)d_in[i + 2];
                    b1  = (const float*)d_in[i + 3];
                }
                break;
            case D1 * NCLS:
                W2  = (const float*)d_in[i];
                if (i + 3 < n_in) {
                    as2 = (const float*)d_in[i + 1];
                    ad2 = (const float*)d_in[i + 2];
                    b2  = (const float*)d_in[i + 3];
                }
                break;
            default: break;
        }
    }

    float* out = (float*)d_out;
    const int TPB = 256;

    cudaFuncSetAttribute(k_gemm1_mma, cudaFuncAttributeMaxDynamicSharedMemorySize, SMEM_G1);

    k_zero<<<(N2V * NCLS + TPB - 1) / TPB, TPB>>>();                 // 1
    k_prep_w<<<160, TPB>>>(W1);                                       // 2
    k_prep_e<<<512, TPB>>>(e1, e2);                                   // 3
    k_gemm1_mma<<<(N0 + 127) / 128, TPB, SMEM_G1>>>(x, as1, ad1);     // 4 <- profiled
    k_edge1_fused<<<(N1V + 7) / 8, TPB>>>(b1);                        // 5
    k_gemm2<<<(N1V * NCLS + TPB - 1) / TPB, TPB>>>(W2);               // 6
    k_att2<<<(N1V + TPB - 1) / TPB, TPB>>>(as2, ad2);                 // 7
    k_edge2_sum<<<(EL2 + TPB - 1) / TPB, TPB>>>();                    // 8
    k_edge2_agg<<<(EL2 * NCLS + TPB - 1) / TPB, TPB>>>();             // 9
    k_final<<<N2V, 32>>>(out, b2);                                    // 10
}

// round 13
// speedup vs baseline: 1.2692x; 1.1278x over previous
#include <cuda_runtime.h>
#include <cuda_bf16.h>
#include <cuda_fp16.h>
#include <math.h>

#define N0   120000
#define N1V  12000
#define N2V  1024
#define E1N  300000
#define E2N  10240
#define F_IN 602
#define H1N  8
#define C1N  8
#define D1   64
#define NCLS 41
#define NEG  0.2f

#define EL1  (E1N + N1V)   // 312000
#define EL2  (E2N + N2V)   // 11264
#define KPAD 608
#define CAP  128

// ---------------- scratch ----------------
__device__ float          g_Hfull[(size_t)N0 * D1];
__device__ float          g_as1[N0 * H1N];
__device__ float          g_ad1[N1V * H1N];
__device__ float          g_out1[N1V * D1];
__device__ float          g_H2[N1V * NCLS];
__device__ float          g_as2[N1V];
__device__ float          g_ad2[N2V];
__device__ float          g_s2[N2V];
__device__ float          g_out2[N2V * NCLS];
__device__ __half         g_W1h[D1 * KPAD];   // fp16(W1), [n][kpad]
__device__ int2           g_e2sd[EL2];
__device__ int            g_cnt1[N1V];
__device__ int            g_nbr1[N1V * CAP];

// ================= launch 1: zero =================
__global__ void k_zero() {
    int i = blockIdx.x * blockDim.x + threadIdx.x;
    if (i < N1V) g_cnt1[i] = 0;
    if (i < N2V * NCLS) g_out2[i] = 0.f;
    if (i < N2V) g_s2[i] = 0.f;
}

// ================= launch 2: W1 fp16 =================
__global__ void k_prep_w(const float* __restrict__ W1) {
    int nt = gridDim.x * blockDim.x;
    for (int i = blockIdx.x * blockDim.x + threadIdx.x; i < D1 * KPAD; i += nt) {
        int n = i / KPAD, k = i - n * KPAD;
        float v = (k < F_IN) ? W1[(size_t)k * D1 + n] : 0.f;
        g_W1h[i] = __float2half_rn(v);
    }
}

// ================= launch 3: edge decode + bucket scatter =================
__global__ void k_prep_e(const void* e1, const void* e2) {
    __shared__ int se64;
    if (threadIdx.x == 0) {
        const long long* p = (const long long*)e1;
        bool ok = true;
        for (int i = 0; i < 16; i++) {
            long long v = p[i];
            if (v < 0 || v >= (long long)N0) { ok = false; break; }
        }
        se64 = ok ? 1 : 0;
    }
    __syncthreads();
    int e64 = se64;
    int nt = gridDim.x * blockDim.x;
    int t0 = blockIdx.x * blockDim.x + threadIdx.x;

    for (int e = t0; e < EL1; e += nt) {
        int s, d;
        if (e < E1N) {
            if (e64) {
                s = (int)((const long long*)e1)[e];
                d = (int)((const long long*)e1)[E1N + e];
            } else {
                s = ((const int*)e1)[e];
                d = ((const int*)e1)[E1N + e];
            }
        } else { s = d = e - E1N; }
        int pos = atomicAdd(&g_cnt1[d], 1);
        if (pos < CAP) g_nbr1[d * CAP + pos] = s;
    }
    for (int e = t0; e < EL2; e += nt) {
        int s, d;
        if (e < E2N) {
            if (e64) {
                s = (int)((const long long*)e2)[e];
                d = (int)((const long long*)e2)[E2N + e];
            } else {
                s = ((const int*)e2)[e];
                d = ((const int*)e2)[E2N + e];
            }
        } else { s = d = e - E2N; }
        g_e2sd[e] = make_int2(s, d);
    }
}

// ================= launch 4: GEMM1 — pure fp16, 256 thr, 8 warps (4Mx2N), 3 CTA/SM =================
#define KC      32
#define NCHUNK  19
#define SA_U32  20
#define SRB     80
#define OFF_AH  0            // 128*80 = 10240
#define OFF_BH  10240        // 64*80  = 5120
#define BUFB    15360
#define SMEM_G1 36864        // max(2*BUFB=30720, C staging 128*72*4=36864)
#define CS_STRIDE 72

__device__ __forceinline__ unsigned smem_u32(const void* p) {
    unsigned a;
    asm("{ .reg .u64 t; cvta.to.shared.u64 t, %1; cvt.u32.u64 %0, t; }" : "=r"(a) : "l"(p));
    return a;
}

__device__ __forceinline__ unsigned cvt2h1(float2 v) {
    __half2 h = __float22half2_rn(v);
    return *(unsigned*)&h;
}

__device__ __forceinline__ void mma_f16(float* c, const unsigned* a, unsigned b0, unsigned b1) {
    asm volatile(
        "mma.sync.aligned.m16n8k16.row.col.f32.f16.f16.f32 "
        "{%0,%1,%2,%3}, {%4,%5,%6,%7}, {%8,%9}, {%0,%1,%2,%3};"
        : "+f"(c[0]), "+f"(c[1]), "+f"(c[2]), "+f"(c[3])
        : "r"(a[0]), "r"(a[1]), "r"(a[2]), "r"(a[3]), "r"(b0), "r"(b1));
}

__device__ __forceinline__ void ldm4(unsigned addr, unsigned* r) {
    asm volatile("ldmatrix.sync.aligned.m8n8.x4.shared.b16 {%0,%1,%2,%3}, [%4];"
                 : "=r"(r[0]), "=r"(r[1]), "=r"(r[2]), "=r"(r[3]) : "r"(addr));
}

__device__ __forceinline__ void cpa16(unsigned dst, const void* src) {
    asm volatile("cp.async.cg.shared.global [%0], [%1], 16;" :: "r"(dst), "l"(src));
}

__global__ void __launch_bounds__(256, 3)
k_gemm1_mma(const float* __restrict__ x,
            const float* __restrict__ a_src, const float* __restrict__ a_dst) {
    extern __shared__ unsigned char smem[];
    unsigned sb = smem_u32(smem);
    int t = threadIdx.x;
    int w = t >> 5, lane = t & 31;
    int g = lane >> 2, tig = lane & 3;
    int wm = w & 3, wn = w >> 2;     // 4M x 2N warps, warp tile 32x32
    int row0 = blockIdx.x * 128;

    float acc[2][4][4];
#pragma unroll
    for (int mi = 0; mi < 2; mi++)
#pragma unroll
        for (int ni = 0; ni < 4; ni++)
#pragma unroll
            for (int q = 0; q < 4; q++) acc[mi][ni][q] = 0.f;

    // B cp.async: 64 rows x 64B = 256 16B ops, one per thread
    int bn = t >> 2, bq = t & 3;
    unsigned bdst_off = (unsigned)(bn * SRB + bq * 16);
    int bsrc_elem = bn * KPAD + bq * 8;

    int arow = ((lane >> 3) & 1) * 8 + (lane & 7);
    unsigned a_loff = (unsigned)((wm * 32 + arow) * SRB + (lane >> 4) * 16);
    int brow = ((lane >> 4) << 3) + (lane & 7);
    unsigned b_loff = (unsigned)((wn * 32 + brow) * SRB + ((lane >> 3) & 1) * 16);

    // -------- prologue: chunk 0 --------
    {
        unsigned* Ah = (unsigned*)(smem + OFF_AH);
#pragma unroll
        for (int j = 0; j < 8; j++) {
            int idx = t + 256 * j;
            int row = idx >> 4, kq = idx & 15;
            float2 v = make_float2(0.f, 0.f);
            if (row0 + row < N0)
                v = *(const float2*)(x + (size_t)(row0 + row) * F_IN + 2 * kq);
            Ah[row * SA_U32 + kq] = cvt2h1(v);
        }
        cpa16(sb + OFF_BH + bdst_off, (const void*)(g_W1h + bsrc_elem));
        asm volatile("cp.async.commit_group;");
        asm volatile("cp.async.wait_group 0;");
    }
    __syncthreads();

    for (int c = 0; c < NCHUNK; c++) {
        int cur = c & 1, nxt = cur ^ 1;
        bool have_next = (c + 1 < NCHUNK);
        float2 av[8];
        if (have_next) {
            int k0 = (c + 1) * KC;
            cpa16(sb + nxt * BUFB + OFF_BH + bdst_off, (const void*)(g_W1h + bsrc_elem + k0));
            asm volatile("cp.async.commit_group;");
#pragma unroll
            for (int j = 0; j < 8; j++) {
                int idx = t + 256 * j;
                int row = idx >> 4, kq = idx & 15;
                int gk = k0 + 2 * kq;
                float2 v = make_float2(0.f, 0.f);
                if (row0 + row < N0 && gk < F_IN)
                    v = *(const float2*)(x + (size_t)(row0 + row) * F_IN + gk);
                av[j] = v;
            }
        }
        // -------- compute on current buffer: Ah x Bh --------
        {
            unsigned abh = sb + cur * BUFB + OFF_AH + a_loff;
            unsigned bbh = sb + cur * BUFB + OFF_BH + b_loff;
#pragma unroll
            for (int kb = 0; kb < 2; kb++) {
                unsigned ko = kb * 32;
                unsigned ah[2][4], bh[2][4];
#pragma unroll
                for (int mi = 0; mi < 2; mi++)
                    ldm4(abh + mi * (16 * SRB) + ko, ah[mi]);
#pragma unroll
                for (int nb = 0; nb < 2; nb++)
                    ldm4(bbh + nb * (16 * SRB) + ko, bh[nb]);
#pragma unroll
                for (int mi = 0; mi < 2; mi++)
#pragma unroll
                    for (int nb = 0; nb < 2; nb++) {
                        mma_f16(acc[mi][nb * 2 + 0], ah[mi], bh[nb][0], bh[nb][1]);
                        mma_f16(acc[mi][nb * 2 + 1], ah[mi], bh[nb][2], bh[nb][3]);
                    }
            }
        }
        if (have_next) {
            unsigned* Ah = (unsigned*)(smem + nxt * BUFB + OFF_AH);
#pragma unroll
            for (int j = 0; j < 8; j++) {
                int idx = t + 256 * j;
                int row = idx >> 4, kq = idx & 15;
                Ah[row * SA_U32 + kq] = cvt2h1(av[j]);
            }
        }
        asm volatile("cp.async.wait_group 0;");
        __syncthreads();
    }

    // -------- epilogue --------
    float* Cs = (float*)smem;
#pragma unroll
    for (int mi = 0; mi < 2; mi++)
#pragma unroll
        for (int ni = 0; ni < 4; ni++) {
            int r = wm * 32 + mi * 16 + g;
            int cc = wn * 32 + ni * 8 + tig * 2;
            Cs[r * CS_STRIDE + cc]           = acc[mi][ni][0];
            Cs[r * CS_STRIDE + cc + 1]       = acc[mi][ni][1];
            Cs[(r + 8) * CS_STRIDE + cc]     = acc[mi][ni][2];
            Cs[(r + 8) * CS_STRIDE + cc + 1] = acc[mi][ni][3];
        }
    __syncthreads();

#pragma unroll
    for (int it = 0; it < 8; it++) {
        int r = (t >> 4) + 16 * it;
        int c4 = (t & 15) * 4;
        if (row0 + r < N0) {
            float4 v = *(const float4*)(Cs + r * CS_STRIDE + c4);
            *(float4*)(g_Hfull + (size_t)(row0 + r) * D1 + c4) = v;
        }
    }
    if (t < 128) {
        int m = row0 + t;
        if (m < N0) {
            const float* rr = Cs + t * CS_STRIDE;
#pragma unroll
            for (int h = 0; h < H1N; h++) {
                float as = 0.f, ad = 0.f;
#pragma unroll
                for (int cc = 0; cc < C1N; cc++) {
                    float v = rr[h * C1N + cc];
                    as = fmaf(v, __ldg(&a_src[h * C1N + cc]), as);
                    ad = fmaf(v, __ldg(&a_dst[h * C1N + cc]), ad);
                }
                g_as1[m * H1N + h] = as;
                if (m < N1V) g_ad1[m * H1N + h] = ad;
            }
        }
    }
}

// ================= launch 5: fused layer-1 softmax + aggregate =================
#define EXS 9
__global__ void __launch_bounds__(256)
k_edge1_fused(const float* __restrict__ b1) {
    __shared__ float s_ex[8][CAP * EXS];
    __shared__ int   s_nbr[8][CAP];
    int wid = threadIdx.x >> 5, lane = threadIdx.x & 31;
    int node = blockIdx.x * 8 + wid;
    if (node >= N1V) return;
    int deg = g_cnt1[node];
    if (deg > CAP) deg = CAP;
    float* exs = s_ex[wid];
    int* nbs = s_nbr[wid];

    float4 adA = __ldg((const float4*)&g_ad1[node * 8]);
    float4 adB = __ldg((const float4*)&g_ad1[node * 8 + 4]);
    float sum[8] = {0.f, 0.f, 0.f, 0.f, 0.f, 0.f, 0.f, 0.f};

    for (int e = lane; e < deg; e += 32) {
        int s = __ldg(&g_nbr1[node * CAP + e]);
        nbs[e] = s;
        float4 sa = __ldg((const float4*)&g_as1[s * 8]);
        float4 sbv = __ldg((const float4*)&g_as1[s * 8 + 4]);
        float a[8] = { sa.x + adA.x, sa.y + adA.y, sa.z + adA.z, sa.w + adA.w,
                       sbv.x + adB.x, sbv.y + adB.y, sbv.z + adB.z, sbv.w + adB.w };
#pragma unroll
        for (int h = 0; h < 8; h++) {
            float v = a[h] > 0.f ? a[h] : NEG * a[h];
            float ex = expf(v);
            sum[h] += ex;
            exs[e * EXS + h] = ex;
        }
    }
    __syncwarp();
#pragma unroll
    for (int h = 0; h < 8; h++)
#pragma unroll
        for (int o = 16; o > 0; o >>= 1)
            sum[h] += __shfl_xor_sync(0xffffffffu, sum[h], o);

    int myh = lane >> 2;
    float myr = 1.f / (sum[myh] + 1e-16f);

    float ax = 0.f, ay = 0.f;
#pragma unroll 4
    for (int e = 0; e < deg; e++) {
        float wgt = exs[e * EXS + myh] * myr;
        int s = nbs[e];
        float2 hv = __ldg((const float2*)&g_Hfull[(size_t)s * D1 + 2 * lane]);
        ax = fmaf(wgt, hv.x, ax);
        ay = fmaf(wgt, hv.y, ay);
    }
    float bx = __ldg(&b1[2 * lane]), by = __ldg(&b1[2 * lane + 1]);
    float vx = ax + bx; vx = vx > 0.f ? vx : expm1f(vx);
    float vy = ay + by; vy = vy > 0.f ? vy : expm1f(vy);
    *(float2*)&g_out1[node * D1 + 2 * lane] = make_float2(vx, vy);
}

// ================= layer 2 =================
__global__ void k_gemm2(const float* __restrict__ W2) {
    __shared__ float Ws[D1 * NCLS];
    for (int i = threadIdx.x; i < D1 * NCLS; i += blockDim.x) Ws[i] = W2[i];
    __syncthreads();
    int t = blockIdx.x * blockDim.x + threadIdx.x;
    if (t >= N1V * NCLS) return;
    int row = t / NCLS, col = t - row * NCLS;
    const float* hr = g_out1 + row * D1;
    float acc = 0.f;
#pragma unroll
    for (int k = 0; k < D1; k++) acc = fmaf(hr[k], Ws[k * NCLS + col], acc);
    g_H2[t] = acc;
}

__global__ void k_att2(const float* __restrict__ a_src, const float* __restrict__ a_dst) {
    int i = blockIdx.x * blockDim.x + threadIdx.x;
    if (i >= N1V) return;
    const float* hp = g_H2 + i * NCLS;
    float as = 0.f;
#pragma unroll
    for (int c = 0; c < NCLS; c++) as += hp[c] * a_src[c];
    g_as2[i] = as;
    if (i < N2V) {
        float ad = 0.f;
#pragma unroll
        for (int c = 0; c < NCLS; c++) ad += hp[c] * a_dst[c];
        g_ad2[i] = ad;
    }
}

__global__ void k_edge2_sum() {
    int e = blockIdx.x * blockDim.x + threadIdx.x;
    if (e >= EL2) return;
    int2 sd = g_e2sd[e];
    float al = g_as2[sd.x] + g_ad2[sd.y];
    al = al > 0.f ? al : NEG * al;
    atomicAdd(&g_s2[sd.y], expf(al));
}

__global__ void k_edge2_agg() {
    int t = blockIdx.x * blockDim.x + threadIdx.x;
    if (t >= EL2 * NCLS) return;
    int e = t / NCLS, c = t - e * NCLS;
    int2 sd = g_e2sd[e];
    float al = g_as2[sd.x] + g_ad2[sd.y];
    al = al > 0.f ? al : NEG * al;
    float w = expf(al) / (g_s2[sd.y] + 1e-16f);
    atomicAdd(&g_out2[sd.y * NCLS + c], g_H2[sd.x * NCLS + c] * w);
}

__global__ void k_final(float* __restrict__ out, const float* __restrict__ b2) {
    int d = blockIdx.x;
    int lane = threadIdx.x;
    float v0 = (lane < NCLS) ? g_out2[d * NCLS + lane] + b2[lane] : -INFINITY;
    float v1 = (lane + 32 < NCLS) ? g_out2[d * NCLS + lane + 32] + b2[lane + 32] : -INFINITY;
    float m = fmaxf(v0, v1);
#pragma unroll
    for (int o = 16; o > 0; o >>= 1) m = fmaxf(m, __shfl_xor_sync(0xffffffffu, m, o));
    float s = ((lane < NCLS) ? expf(v0 - m) : 0.f) + ((lane + 32 < NCLS) ? expf(v1 - m) : 0.f);
#pragma unroll
    for (int o = 16; o > 0; o >>= 1) s += __shfl_xor_sync(0xffffffffu, s, o);
    float ls = m + logf(s);
    if (lane < NCLS) out[d * NCLS + lane] = v0 - ls;
    if (lane + 32 < NCLS) out[d * NCLS + lane + 32] = v1 - ls;
}

// ---------------- launch ----------------
extern "C" void kernel_launch(void* const* d_in, const int* in_sizes, int n_in,
                              void* d_out, int out_size) {
    const float* x = nullptr;
    const void* e1 = nullptr;
    const void* e2 = nullptr;
    const float *W1 = nullptr, *as1 = nullptr, *ad1 = nullptr, *b1 = nullptr;
    const float *W2 = nullptr, *as2 = nullptr, *ad2 = nullptr, *b2 = nullptr;

    for (int i = 0; i < n_in; i++) {
        switch (in_sizes[i]) {
            case N0 * F_IN:   x  = (const float*)d_in[i]; break;
            case 2 * E1N:     e1 = d_in[i]; break;
            case 2 * E2N:     e2 = d_in[i]; break;
            case F_IN * D1:
                W1  = (const float*)d_in[i];
                if (i + 3 < n_in) {
                    as1 = (const float*)d_in[i + 1];
                    ad1 = (const float*)d_in[i + 2];
                    b1  = (const float*)d_in[i + 3];
                }
                break;
            case D1 * NCLS:
                W2  = (const float*)d_in[i];
                if (i + 3 < n_in) {
                    as2 = (const float*)d_in[i + 1];
                    ad2 = (const float*)d_in[i + 2];
                    b2  = (const float*)d_in[i + 3];
                }
                break;
            default: break;
        }
    }

    float* out = (float*)d_out;
    const int TPB = 256;

    cudaFuncSetAttribute(k_gemm1_mma, cudaFuncAttributeMaxDynamicSharedMemorySize, SMEM_G1);

    k_zero<<<(N2V * NCLS + TPB - 1) / TPB, TPB>>>();                 // 1
    k_prep_w<<<160, TPB>>>(W1);                                       // 2
    k_prep_e<<<512, TPB>>>(e1, e2);                                   // 3
    k_gemm1_mma<<<(N0 + 127) / 128, TPB, SMEM_G1>>>(x, as1, ad1);     // 4 <- profiled
    k_edge1_fused<<<(N1V + 7) / 8, TPB>>>(b1);                        // 5
    k_gemm2<<<(N1V * NCLS + TPB - 1) / TPB, TPB>>>(W2);               // 6
    k_att2<<<(N1V + TPB - 1) / TPB, TPB>>>(as2, ad2);                 // 7
    k_edge2_sum<<<(EL2 + TPB - 1) / TPB, TPB>>>();                    // 8
    k_edge2_agg<<<(EL2 * NCLS + TPB - 1) / TPB, TPB>>>();             // 9
    k_final<<<N2V, 32>>>(out, b2);                                    // 10
}

// round 14
// speedup vs baseline: 1.2857x; 1.0130x over previous
#include <cuda_runtime.h>
#include <cuda_bf16.h>
#include <cuda_fp16.h>
#include <math.h>

#define N0   120000
#define N1V  12000
#define N2V  1024
#define E1N  300000
#define E2N  10240
#define F_IN 602
#define H1N  8
#define C1N  8
#define D1   64
#define NCLS 41
#define NEG  0.2f

#define EL1  (E1N + N1V)   // 312000
#define EL2  (E2N + N2V)   // 11264
#define KPAD 608
#define CAP  128

// ---------------- scratch ----------------
__device__ float          g_Hfull[(size_t)N0 * D1];
__device__ float          g_as1[N0 * H1N];
__device__ float          g_ad1[N1V * H1N];
__device__ float          g_out1[N1V * D1];
__device__ float          g_H2[N1V * NCLS];
__device__ float          g_as2[N1V];
__device__ float          g_ad2[N2V];
__device__ float          g_s2[N2V];
__device__ float          g_out2[N2V * NCLS];
__device__ __half         g_W1h[D1 * KPAD];   // fp16(W1), [n][kpad]
__device__ int2           g_e2sd[EL2];
__device__ int            g_cnt1[N1V];
__device__ int            g_nbr1[N1V * CAP];

// ================= launch 1: zero =================
__global__ void k_zero() {
    int i = blockIdx.x * blockDim.x + threadIdx.x;
    if (i < N1V) g_cnt1[i] = 0;
    if (i < N2V * NCLS) g_out2[i] = 0.f;
    if (i < N2V) g_s2[i] = 0.f;
}

// ================= launch 2: prep (W1 fp16 + edge decode/scatter) =================
__global__ void k_prep(const float* __restrict__ W1, const void* e1, const void* e2) {
    __shared__ int se64;
    if (threadIdx.x == 0) {
        const long long* p = (const long long*)e1;
        bool ok = true;
        for (int i = 0; i < 16; i++) {
            long long v = p[i];
            if (v < 0 || v >= (long long)N0) { ok = false; break; }
        }
        se64 = ok ? 1 : 0;
    }
    __syncthreads();
    int e64 = se64;
    int nt = gridDim.x * blockDim.x;
    int t0 = blockIdx.x * blockDim.x + threadIdx.x;

    for (int i = t0; i < D1 * KPAD; i += nt) {
        int n = i / KPAD, k = i - n * KPAD;
        float v = (k < F_IN) ? W1[(size_t)k * D1 + n] : 0.f;
        g_W1h[i] = __float2half_rn(v);
    }
    for (int e = t0; e < EL1; e += nt) {
        int s, d;
        if (e < E1N) {
            if (e64) {
                s = (int)((const long long*)e1)[e];
                d = (int)((const long long*)e1)[E1N + e];
            } else {
                s = ((const int*)e1)[e];
                d = ((const int*)e1)[E1N + e];
            }
        } else { s = d = e - E1N; }
        int pos = atomicAdd(&g_cnt1[d], 1);
        if (pos < CAP) g_nbr1[d * CAP + pos] = s;
    }
    for (int e = t0; e < EL2; e += nt) {
        int s, d;
        if (e < E2N) {
            if (e64) {
                s = (int)((const long long*)e2)[e];
                d = (int)((const long long*)e2)[E2N + e];
            } else {
                s = ((const int*)e2)[e];
                d = ((const int*)e2)[E2N + e];
            }
        } else { s = d = e - E2N; }
        g_e2sd[e] = make_int2(s, d);
    }
}

// ================= launch 3: GEMM1 — pure fp16, hoisted A addressing =================
#define KC      32
#define NCHUNK  19
#define SA_U32  20
#define SRB     80
#define OFF_AH  0
#define OFF_BH  10240
#define BUFB    15360
#define SMEM_G1 36864
#define CS_STRIDE 72
#define AROWS   (16 * F_IN)   // float stride between this thread's consecutive A rows

__device__ __forceinline__ unsigned smem_u32(const void* p) {
    unsigned a;
    asm("{ .reg .u64 t; cvta.to.shared.u64 t, %1; cvt.u32.u64 %0, t; }" : "=r"(a) : "l"(p));
    return a;
}

__device__ __forceinline__ unsigned cvt2h1(float2 v) {
    __half2 h = __float22half2_rn(v);
    return *(unsigned*)&h;
}

__device__ __forceinline__ void mma_f16(float* c, const unsigned* a, unsigned b0, unsigned b1) {
    asm volatile(
        "mma.sync.aligned.m16n8k16.row.col.f32.f16.f16.f32 "
        "{%0,%1,%2,%3}, {%4,%5,%6,%7}, {%8,%9}, {%0,%1,%2,%3};"
        : "+f"(c[0]), "+f"(c[1]), "+f"(c[2]), "+f"(c[3])
        : "r"(a[0]), "r"(a[1]), "r"(a[2]), "r"(a[3]), "r"(b0), "r"(b1));
}

__device__ __forceinline__ void ldm4(unsigned addr, unsigned* r) {
    asm volatile("ldmatrix.sync.aligned.m8n8.x4.shared.b16 {%0,%1,%2,%3}, [%4];"
                 : "=r"(r[0]), "=r"(r[1]), "=r"(r[2]), "=r"(r[3]) : "r"(addr));
}

__device__ __forceinline__ void cpa16(unsigned dst, const void* src) {
    asm volatile("cp.async.cg.shared.global [%0], [%1], 16;" :: "r"(dst), "l"(src));
}

__global__ void __launch_bounds__(256, 3)
k_gemm1_mma(const float* __restrict__ x,
            const float* __restrict__ a_src, const float* __restrict__ a_dst) {
    extern __shared__ unsigned char smem[];
    unsigned sb = smem_u32(smem);
    int t = threadIdx.x;
    int w = t >> 5, lane = t & 31;
    int g = lane >> 2, tig = lane & 3;
    int wm = w & 3, wn = w >> 2;     // 4M x 2N warps, warp tile 32x32
    int row0 = blockIdx.x * 128;

    float acc[2][4][4];
#pragma unroll
    for (int mi = 0; mi < 2; mi++)
#pragma unroll
        for (int ni = 0; ni < 4; ni++)
#pragma unroll
            for (int q = 0; q < 4; q++) acc[mi][ni][q] = 0.f;

    // ---- hoisted per-thread A addressing ----
    int r0  = t >> 4;            // base row in tile (0..15)
    int kq2 = (t & 15) * 2;      // base k within chunk (0..30)
    const float* aptr = x + (size_t)(row0 + r0) * F_IN + kq2;
    unsigned amask = 0;
#pragma unroll
    for (int j = 0; j < 8; j++)
        if (row0 + r0 + 16 * j < N0) amask |= 1u << j;
    unsigned a_soff = (unsigned)(r0 * SA_U32 + (t & 15)) * 4;  // byte offset in A smem

    // B cp.async: one 16B op per thread
    int bn = t >> 2, bq = t & 3;
    unsigned bdst_off = (unsigned)(bn * SRB + bq * 16);
    int bsrc_elem = bn * KPAD + bq * 8;

    int arow = ((lane >> 3) & 1) * 8 + (lane & 7);
    unsigned a_loff = (unsigned)((wm * 32 + arow) * SRB + (lane >> 4) * 16);
    int brow = ((lane >> 4) << 3) + (lane & 7);
    unsigned b_loff = (unsigned)((wn * 32 + brow) * SRB + ((lane >> 3) & 1) * 16);

    // -------- prologue: chunk 0 --------
    {
        unsigned* Ah = (unsigned*)(smem + OFF_AH + a_soff);
#pragma unroll
        for (int j = 0; j < 8; j++) {
            float2 v = (amask >> j) & 1 ? *(const float2*)(aptr + j * AROWS)
                                        : make_float2(0.f, 0.f);
            Ah[j * (16 * SA_U32)] = cvt2h1(v);
        }
        cpa16(sb + OFF_BH + bdst_off, (const void*)(g_W1h + bsrc_elem));
        asm volatile("cp.async.commit_group;");
        asm volatile("cp.async.wait_group 0;");
    }
    __syncthreads();

    for (int c = 0; c < NCHUNK; c++) {
        int cur = c & 1, nxt = cur ^ 1;
        bool have_next = (c + 1 < NCHUNK);
        float2 av[8];
        if (have_next) {
            int koff = (c + 1) * KC;
            cpa16(sb + nxt * BUFB + OFF_BH + bdst_off, (const void*)(g_W1h + bsrc_elem + koff));
            asm volatile("cp.async.commit_group;");
            bool colok = (koff + kq2 + 1 < F_IN);
            const float* ap = aptr + koff;
#pragma unroll
            for (int j = 0; j < 8; j++)
                av[j] = (colok && ((amask >> j) & 1)) ? *(const float2*)(ap + j * AROWS)
                                                      : make_float2(0.f, 0.f);
        }
        // -------- compute on current buffer: Ah x Bh --------
        {
            unsigned abh = sb + cur * BUFB + OFF_AH + a_loff;
            unsigned bbh = sb + cur * BUFB + OFF_BH + b_loff;
#pragma unroll
            for (int kb = 0; kb < 2; kb++) {
                unsigned ko = kb * 32;
                unsigned ah[2][4], bh[2][4];
#pragma unroll
                for (int mi = 0; mi < 2; mi++)
                    ldm4(abh + mi * (16 * SRB) + ko, ah[mi]);
#pragma unroll
                for (int nb = 0; nb < 2; nb++)
                    ldm4(bbh + nb * (16 * SRB) + ko, bh[nb]);
#pragma unroll
                for (int mi = 0; mi < 2; mi++)
#pragma unroll
                    for (int nb = 0; nb < 2; nb++) {
                        mma_f16(acc[mi][nb * 2 + 0], ah[mi], bh[nb][0], bh[nb][1]);
                        mma_f16(acc[mi][nb * 2 + 1], ah[mi], bh[nb][2], bh[nb][3]);
                    }
            }
        }
        if (have_next) {
            unsigned* Ah = (unsigned*)(smem + nxt * BUFB + OFF_AH + a_soff);
#pragma unroll
            for (int j = 0; j < 8; j++)
                Ah[j * (16 * SA_U32)] = cvt2h1(av[j]);
        }
        asm volatile("cp.async.wait_group 0;");
        __syncthreads();
    }

    // -------- epilogue --------
    float* Cs = (float*)smem;
#pragma unroll
    for (int mi = 0; mi < 2; mi++)
#pragma unroll
        for (int ni = 0; ni < 4; ni++) {
            int r = wm * 32 + mi * 16 + g;
            int cc = wn * 32 + ni * 8 + tig * 2;
            Cs[r * CS_STRIDE + cc]           = acc[mi][ni][0];
            Cs[r * CS_STRIDE + cc + 1]       = acc[mi][ni][1];
            Cs[(r + 8) * CS_STRIDE + cc]     = acc[mi][ni][2];
            Cs[(r + 8) * CS_STRIDE + cc + 1] = acc[mi][ni][3];
        }
    __syncthreads();

#pragma unroll
    for (int it = 0; it < 8; it++) {
        int r = (t >> 4) + 16 * it;
        int c4 = (t & 15) * 4;
        if (row0 + r < N0) {
            float4 v = *(const float4*)(Cs + r * CS_STRIDE + c4);
            *(float4*)(g_Hfull + (size_t)(row0 + r) * D1 + c4) = v;
        }
    }
    if (t < 128) {
        int m = row0 + t;
        if (m < N0) {
            const float* rr = Cs + t * CS_STRIDE;
#pragma unroll
            for (int h = 0; h < H1N; h++) {
                float as = 0.f, ad = 0.f;
#pragma unroll
                for (int cc = 0; cc < C1N; cc++) {
                    float v = rr[h * C1N + cc];
                    as = fmaf(v, __ldg(&a_src[h * C1N + cc]), as);
                    ad = fmaf(v, __ldg(&a_dst[h * C1N + cc]), ad);
                }
                g_as1[m * H1N + h] = as;
                if (m < N1V) g_ad1[m * H1N + h] = ad;
            }
        }
    }
}

// ================= launch 4: fused layer-1 softmax + aggregate (profiled) =================
#define EXS 9
__global__ void __launch_bounds__(256)
k_edge1_fused(const float* __restrict__ b1) {
    __shared__ float s_ex[8][CAP * EXS];
    __shared__ int   s_nbr[8][CAP];
    int wid = threadIdx.x >> 5, lane = threadIdx.x & 31;
    int node = blockIdx.x * 8 + wid;
    if (node >= N1V) return;
    int deg = g_cnt1[node];
    if (deg > CAP) deg = CAP;
    float* exs = s_ex[wid];
    int* nbs = s_nbr[wid];

    float4 adA = __ldg((const float4*)&g_ad1[node * 8]);
    float4 adB = __ldg((const float4*)&g_ad1[node * 8 + 4]);
    float sum[8] = {0.f, 0.f, 0.f, 0.f, 0.f, 0.f, 0.f, 0.f};

    for (int e = lane; e < deg; e += 32) {
        int s = __ldg(&g_nbr1[node * CAP + e]);
        nbs[e] = s;
        float4 sa = __ldg((const float4*)&g_as1[s * 8]);
        float4 sbv = __ldg((const float4*)&g_as1[s * 8 + 4]);
        float a[8] = { sa.x + adA.x, sa.y + adA.y, sa.z + adA.z, sa.w + adA.w,
                       sbv.x + adB.x, sbv.y + adB.y, sbv.z + adB.z, sbv.w + adB.w };
#pragma unroll
        for (int h = 0; h < 8; h++) {
            float v = a[h] > 0.f ? a[h] : NEG * a[h];
            float ex = expf(v);
            sum[h] += ex;
            exs[e * EXS + h] = ex;
        }
    }
    __syncwarp();
#pragma unroll
    for (int h = 0; h < 8; h++)
#pragma unroll
        for (int o = 16; o > 0; o >>= 1)
            sum[h] += __shfl_xor_sync(0xffffffffu, sum[h], o);

    int myh = lane >> 2;
    float myr = 1.f / (sum[myh] + 1e-16f);

    float ax = 0.f, ay = 0.f;
#pragma unroll 4
    for (int e = 0; e < deg; e++) {
        float wgt = exs[e * EXS + myh] * myr;
        int s = nbs[e];
        float2 hv = __ldg((const float2*)&g_Hfull[(size_t)s * D1 + 2 * lane]);
        ax = fmaf(wgt, hv.x, ax);
        ay = fmaf(wgt, hv.y, ay);
    }
    float bx = __ldg(&b1[2 * lane]), by = __ldg(&b1[2 * lane + 1]);
    float vx = ax + bx; vx = vx > 0.f ? vx : expm1f(vx);
    float vy = ay + by; vy = vy > 0.f ? vy : expm1f(vy);
    *(float2*)&g_out1[node * D1 + 2 * lane] = make_float2(vx, vy);
}

// ================= layer 2 =================
__global__ void k_gemm2(const float* __restrict__ W2) {
    __shared__ float Ws[D1 * NCLS];
    for (int i = threadIdx.x; i < D1 * NCLS; i += blockDim.x) Ws[i] = W2[i];
    __syncthreads();
    int t = blockIdx.x * blockDim.x + threadIdx.x;
    if (t >= N1V * NCLS) return;
    int row = t / NCLS, col = t - row * NCLS;
    const float* hr = g_out1 + row * D1;
    float acc = 0.f;
#pragma unroll
    for (int k = 0; k < D1; k++) acc = fmaf(hr[k], Ws[k * NCLS + col], acc);
    g_H2[t] = acc;
}

__global__ void k_att2(const float* __restrict__ a_src, const float* __restrict__ a_dst) {
    int i = blockIdx.x * blockDim.x + threadIdx.x;
    if (i >= N1V) return;
    const float* hp = g_H2 + i * NCLS;
    float as = 0.f;
#pragma unroll
    for (int c = 0; c < NCLS; c++) as += hp[c] * a_src[c];
    g_as2[i] = as;
    if (i < N2V) {
        float ad = 0.f;
#pragma unroll
        for (int c = 0; c < NCLS; c++) ad += hp[c] * a_dst[c];
        g_ad2[i] = ad;
    }
}

__global__ void k_edge2_sum() {
    int e = blockIdx.x * blockDim.x + threadIdx.x;
    if (e >= EL2) return;
    int2 sd = g_e2sd[e];
    float al = g_as2[sd.x] + g_ad2[sd.y];
    al = al > 0.f ? al : NEG * al;
    atomicAdd(&g_s2[sd.y], expf(al));
}

__global__ void k_edge2_agg() {
    int t = blockIdx.x * blockDim.x + threadIdx.x;
    if (t >= EL2 * NCLS) return;
    int e = t / NCLS, c = t - e * NCLS;
    int2 sd = g_e2sd[e];
    float al = g_as2[sd.x] + g_ad2[sd.y];
    al = al > 0.f ? al : NEG * al;
    float w = expf(al) / (g_s2[sd.y] + 1e-16f);
    atomicAdd(&g_out2[sd.y * NCLS + c], g_H2[sd.x * NCLS + c] * w);
}

__global__ void k_final(float* __restrict__ out, const float* __restrict__ b2) {
    int d = blockIdx.x;
    int lane = threadIdx.x;
    float v0 = (lane < NCLS) ? g_out2[d * NCLS + lane] + b2[lane] : -INFINITY;
    float v1 = (lane + 32 < NCLS) ? g_out2[d * NCLS + lane + 32] + b2[lane + 32] : -INFINITY;
    float m = fmaxf(v0, v1);
#pragma unroll
    for (int o = 16; o > 0; o >>= 1) m = fmaxf(m, __shfl_xor_sync(0xffffffffu, m, o));
    float s = ((lane < NCLS) ? expf(v0 - m) : 0.f) + ((lane + 32 < NCLS) ? expf(v1 - m) : 0.f);
#pragma unroll
    for (int o = 16; o > 0; o >>= 1) s += __shfl_xor_sync(0xffffffffu, s, o);
    float ls = m + logf(s);
    if (lane < NCLS) out[d * NCLS + lane] = v0 - ls;
    if (lane + 32 < NCLS) out[d * NCLS + lane + 32] = v1 - ls;
}

// ---------------- launch ----------------
extern "C" void kernel_launch(void* const* d_in, const int* in_sizes, int n_in,
                              void* d_out, int out_size) {
    const float* x = nullptr;
    const void* e1 = nullptr;
    const void* e2 = nullptr;
    const float *W1 = nullptr, *as1 = nullptr, *ad1 = nullptr, *b1 = nullptr;
    const float *W2 = nullptr, *as2 = nullptr, *ad2 = nullptr, *b2 = nullptr;

    for (int i = 0; i < n_in; i++) {
        switch (in_sizes[i]) {
            case N0 * F_IN:   x  = (const float*)d_in[i]; break;
            case 2 * E1N:     e1 = d_in[i]; break;
            case 2 * E2N:     e2 = d_in[i]; break;
            case F_IN * D1:
                W1  = (const float*)d_in[i];
                if (i + 3 < n_in) {
                    as1 = (const float*)d_in[i + 1];
                    ad1 = (const float*)d_in[i + 2];
                    b1  = (const float*)d_in[i + 3];
                }
                break;
            case D1 * NCLS:
                W2  = (const float*)d_in[i];
                if (i + 3 < n_in) {
                    as2 = (const float*)d_in[i + 1];
                    ad2 = (const float*)d_in[i + 2];
                    b2  = (const float*)d_in[i + 3];
                }
                break;
            default: break;
        }
    }

    float* out = (float*)d_out;
    const int TPB = 256;

    cudaFuncSetAttribute(k_gemm1_mma, cudaFuncAttributeMaxDynamicSharedMemorySize, SMEM_G1);

    k_zero<<<(N2V * NCLS + TPB - 1) / TPB, TPB>>>();                 // 1
    k_prep<<<512, TPB>>>(W1, e1, e2);                                 // 2
    k_gemm1_mma<<<(N0 + 127) / 128, TPB, SMEM_G1>>>(x, as1, ad1);     // 3
    k_edge1_fused<<<(N1V + 7) / 8, TPB>>>(b1);                        // 4 <- profiled
    k_gemm2<<<(N1V * NCLS + TPB - 1) / TPB, TPB>>>(W2);               // 5
    k_att2<<<(N1V + TPB - 1) / TPB, TPB>>>(as2, ad2);                 // 6
    k_edge2_sum<<<(EL2 + TPB - 1) / TPB, TPB>>>();                    // 7
    k_edge2_agg<<<(EL2 * NCLS + TPB - 1) / TPB, TPB>>>();             // 8
    k_final<<<N2V, 32>>>(out, b2);                                    // 9
}

// round 15
// speedup vs baseline: 1.2917x; 1.0047x over previous
#include <cuda_runtime.h>
#include <cuda_bf16.h>
#include <cuda_fp16.h>
#include <math.h>

#define N0   120000
#define N1V  12000
#define N2V  1024
#define E1N  300000
#define E2N  10240
#define F_IN 602
#define H1N  8
#define C1N  8
#define D1   64
#define NCLS 41
#define NEG  0.2f

#define EL1  (E1N + N1V)   // 312000
#define EL2  (E2N + N2V)   // 11264
#define KPAD 608
#define CAP  128

// ---------------- scratch ----------------
__device__ float          g_Hfull[(size_t)N0 * D1];
__device__ float          g_as1[N0 * H1N];
__device__ float          g_ad1[N1V * H1N];
__device__ float          g_ex1[(size_t)N1V * CAP * H1N];   // exp cache (49 MB)
__device__ float          g_out1[N1V * D1];
__device__ float          g_H2[N1V * NCLS];
__device__ float          g_as2[N1V];
__device__ float          g_ad2[N2V];
__device__ float          g_s2[N2V];
__device__ float          g_out2[N2V * NCLS];
__device__ __half         g_W1h[D1 * KPAD];   // fp16(W1), [n][kpad]
__device__ int2           g_e2sd[EL2];
__device__ int            g_cnt1[N1V];
__device__ int            g_nbr1[N1V * CAP];

// ================= zero =================
__global__ void k_zero() {
    int i = blockIdx.x * blockDim.x + threadIdx.x;
    if (i < N1V) g_cnt1[i] = 0;
    if (i < N2V * NCLS) g_out2[i] = 0.f;
    if (i < N2V) g_s2[i] = 0.f;
}

// ================= prep (W1 fp16 + edge decode/scatter) =================
__global__ void k_prep(const float* __restrict__ W1, const void* e1, const void* e2) {
    __shared__ int se64;
    if (threadIdx.x == 0) {
        const long long* p = (const long long*)e1;
        bool ok = true;
        for (int i = 0; i < 16; i++) {
            long long v = p[i];
            if (v < 0 || v >= (long long)N0) { ok = false; break; }
        }
        se64 = ok ? 1 : 0;
    }
    __syncthreads();
    int e64 = se64;
    int nt = gridDim.x * blockDim.x;
    int t0 = blockIdx.x * blockDim.x + threadIdx.x;

    for (int i = t0; i < D1 * KPAD; i += nt) {
        int n = i / KPAD, k = i - n * KPAD;
        float v = (k < F_IN) ? W1[(size_t)k * D1 + n] : 0.f;
        g_W1h[i] = __float2half_rn(v);
    }
    for (int e = t0; e < EL1; e += nt) {
        int s, d;
        if (e < E1N) {
            if (e64) {
                s = (int)((const long long*)e1)[e];
                d = (int)((const long long*)e1)[E1N + e];
            } else {
                s = ((const int*)e1)[e];
                d = ((const int*)e1)[E1N + e];
            }
        } else { s = d = e - E1N; }
        int pos = atomicAdd(&g_cnt1[d], 1);
        if (pos < CAP) g_nbr1[d * CAP + pos] = s;
    }
    for (int e = t0; e < EL2; e += nt) {
        int s, d;
        if (e < E2N) {
            if (e64) {
                s = (int)((const long long*)e2)[e];
                d = (int)((const long long*)e2)[E2N + e];
            } else {
                s = ((const int*)e2)[e];
                d = ((const int*)e2)[E2N + e];
            }
        } else { s = d = e - E2N; }
        g_e2sd[e] = make_int2(s, d);
    }
}

// ================= GEMM1 — pure fp16, hoisted A addressing (unchanged from R13) =================
#define KC      32
#define NCHUNK  19
#define SA_U32  20
#define SRB     80
#define OFF_AH  0
#define OFF_BH  10240
#define BUFB    15360
#define SMEM_G1 36864
#define CS_STRIDE 72
#define AROWS   (16 * F_IN)

__device__ __forceinline__ unsigned smem_u32(const void* p) {
    unsigned a;
    asm("{ .reg .u64 t; cvta.to.shared.u64 t, %1; cvt.u32.u64 %0, t; }" : "=r"(a) : "l"(p));
    return a;
}

__device__ __forceinline__ unsigned cvt2h1(float2 v) {
    __half2 h = __float22half2_rn(v);
    return *(unsigned*)&h;
}

__device__ __forceinline__ void mma_f16(float* c, const unsigned* a, unsigned b0, unsigned b1) {
    asm volatile(
        "mma.sync.aligned.m16n8k16.row.col.f32.f16.f16.f32 "
        "{%0,%1,%2,%3}, {%4,%5,%6,%7}, {%8,%9}, {%0,%1,%2,%3};"
        : "+f"(c[0]), "+f"(c[1]), "+f"(c[2]), "+f"(c[3])
        : "r"(a[0]), "r"(a[1]), "r"(a[2]), "r"(a[3]), "r"(b0), "r"(b1));
}

__device__ __forceinline__ void ldm4(unsigned addr, unsigned* r) {
    asm volatile("ldmatrix.sync.aligned.m8n8.x4.shared.b16 {%0,%1,%2,%3}, [%4];"
                 : "=r"(r[0]), "=r"(r[1]), "=r"(r[2]), "=r"(r[3]) : "r"(addr));
}

__device__ __forceinline__ void cpa16(unsigned dst, const void* src) {
    asm volatile("cp.async.cg.shared.global [%0], [%1], 16;" :: "r"(dst), "l"(src));
}

__global__ void __launch_bounds__(256, 3)
k_gemm1_mma(const float* __restrict__ x,
            const float* __restrict__ a_src, const float* __restrict__ a_dst) {
    extern __shared__ unsigned char smem[];
    unsigned sb = smem_u32(smem);
    int t = threadIdx.x;
    int w = t >> 5, lane = t & 31;
    int g = lane >> 2, tig = lane & 3;
    int wm = w & 3, wn = w >> 2;
    int row0 = blockIdx.x * 128;

    float acc[2][4][4];
#pragma unroll
    for (int mi = 0; mi < 2; mi++)
#pragma unroll
        for (int ni = 0; ni < 4; ni++)
#pragma unroll
            for (int q = 0; q < 4; q++) acc[mi][ni][q] = 0.f;

    int r0  = t >> 4;
    int kq2 = (t & 15) * 2;
    const float* aptr = x + (size_t)(row0 + r0) * F_IN + kq2;
    unsigned amask = 0;
#pragma unroll
    for (int j = 0; j < 8; j++)
        if (row0 + r0 + 16 * j < N0) amask |= 1u << j;
    unsigned a_soff = (unsigned)(r0 * SA_U32 + (t & 15)) * 4;

    int bn = t >> 2, bq = t & 3;
    unsigned bdst_off = (unsigned)(bn * SRB + bq * 16);
    int bsrc_elem = bn * KPAD + bq * 8;

    int arow = ((lane >> 3) & 1) * 8 + (lane & 7);
    unsigned a_loff = (unsigned)((wm * 32 + arow) * SRB + (lane >> 4) * 16);
    int brow = ((lane >> 4) << 3) + (lane & 7);
    unsigned b_loff = (unsigned)((wn * 32 + brow) * SRB + ((lane >> 3) & 1) * 16);

    {
        unsigned* Ah = (unsigned*)(smem + OFF_AH + a_soff);
#pragma unroll
        for (int j = 0; j < 8; j++) {
            float2 v = (amask >> j) & 1 ? *(const float2*)(aptr + j * AROWS)
                                        : make_float2(0.f, 0.f);
            Ah[j * (16 * SA_U32)] = cvt2h1(v);
        }
        cpa16(sb + OFF_BH + bdst_off, (const void*)(g_W1h + bsrc_elem));
        asm volatile("cp.async.commit_group;");
        asm volatile("cp.async.wait_group 0;");
    }
    __syncthreads();

    for (int c = 0; c < NCHUNK; c++) {
        int cur = c & 1, nxt = cur ^ 1;
        bool have_next = (c + 1 < NCHUNK);
        float2 av[8];
        if (have_next) {
            int koff = (c + 1) * KC;
            cpa16(sb + nxt * BUFB + OFF_BH + bdst_off, (const void*)(g_W1h + bsrc_elem + koff));
            asm volatile("cp.async.commit_group;");
            bool colok = (koff + kq2 + 1 < F_IN);
            const float* ap = aptr + koff;
#pragma unroll
            for (int j = 0; j < 8; j++)
                av[j] = (colok && ((amask >> j) & 1)) ? *(const float2*)(ap + j * AROWS)
                                                      : make_float2(0.f, 0.f);
        }
        {
            unsigned abh = sb + cur * BUFB + OFF_AH + a_loff;
            unsigned bbh = sb + cur * BUFB + OFF_BH + b_loff;
#pragma unroll
            for (int kb = 0; kb < 2; kb++) {
                unsigned ko = kb * 32;
                unsigned ah[2][4], bh[2][4];
#pragma unroll
                for (int mi = 0; mi < 2; mi++)
                    ldm4(abh + mi * (16 * SRB) + ko, ah[mi]);
#pragma unroll
                for (int nb = 0; nb < 2; nb++)
                    ldm4(bbh + nb * (16 * SRB) + ko, bh[nb]);
#pragma unroll
                for (int mi = 0; mi < 2; mi++)
#pragma unroll
                    for (int nb = 0; nb < 2; nb++) {
                        mma_f16(acc[mi][nb * 2 + 0], ah[mi], bh[nb][0], bh[nb][1]);
                        mma_f16(acc[mi][nb * 2 + 1], ah[mi], bh[nb][2], bh[nb][3]);
                    }
            }
        }
        if (have_next) {
            unsigned* Ah = (unsigned*)(smem + nxt * BUFB + OFF_AH + a_soff);
#pragma unroll
            for (int j = 0; j < 8; j++)
                Ah[j * (16 * SA_U32)] = cvt2h1(av[j]);
        }
        asm volatile("cp.async.wait_group 0;");
        __syncthreads();
    }

    float* Cs = (float*)smem;
#pragma unroll
    for (int mi = 0; mi < 2; mi++)
#pragma unroll
        for (int ni = 0; ni < 4; ni++) {
            int r = wm * 32 + mi * 16 + g;
            int cc = wn * 32 + ni * 8 + tig * 2;
            Cs[r * CS_STRIDE + cc]           = acc[mi][ni][0];
            Cs[r * CS_STRIDE + cc + 1]       = acc[mi][ni][1];
            Cs[(r + 8) * CS_STRIDE + cc]     = acc[mi][ni][2];
            Cs[(r + 8) * CS_STRIDE + cc + 1] = acc[mi][ni][3];
        }
    __syncthreads();

#pragma unroll
    for (int it = 0; it < 8; it++) {
        int r = (t >> 4) + 16 * it;
        int c4 = (t & 15) * 4;
        if (row0 + r < N0) {
            float4 v = *(const float4*)(Cs + r * CS_STRIDE + c4);
            *(float4*)(g_Hfull + (size_t)(row0 + r) * D1 + c4) = v;
        }
    }
    if (t < 128) {
        int m = row0 + t;
        if (m < N0) {
            const float* rr = Cs + t * CS_STRIDE;
#pragma unroll
            for (int h = 0; h < H1N; h++) {
                float as = 0.f, ad = 0.f;
#pragma unroll
                for (int cc = 0; cc < C1N; cc++) {
                    float v = rr[h * C1N + cc];
                    as = fmaf(v, __ldg(&a_src[h * C1N + cc]), as);
                    ad = fmaf(v, __ldg(&a_dst[h * C1N + cc]), ad);
                }
                g_as1[m * H1N + h] = as;
                if (m < N1V) g_ad1[m * H1N + h] = ad;
            }
        }
    }
}

// ================= fused layer-1 softmax + aggregate (global ex, deep MLP) =================
__global__ void __launch_bounds__(256)
k_edge1_fused(const float* __restrict__ b1) {
    int node = (blockIdx.x * blockDim.x + threadIdx.x) >> 5;
    int lane = threadIdx.x & 31;
    if (node >= N1V) return;
    int deg = g_cnt1[node];
    if (deg > CAP) deg = CAP;
    const int* nbr = g_nbr1 + node * CAP;
    float* exb = g_ex1 + (size_t)node * CAP * 8;

    float4 adA = __ldg((const float4*)&g_ad1[node * 8]);
    float4 adB = __ldg((const float4*)&g_ad1[node * 8 + 4]);
    float sum[8] = {0.f, 0.f, 0.f, 0.f, 0.f, 0.f, 0.f, 0.f};

    // phase 1: exp per (edge, head); cache; partial head-sums
    for (int e = lane; e < deg; e += 32) {
        int s = __ldg(&nbr[e]);
        float4 sa = __ldg((const float4*)&g_as1[s * 8]);
        float4 sbv = __ldg((const float4*)&g_as1[s * 8 + 4]);
        float a[8] = { sa.x + adA.x, sa.y + adA.y, sa.z + adA.z, sa.w + adA.w,
                       sbv.x + adB.x, sbv.y + adB.y, sbv.z + adB.z, sbv.w + adB.w };
        float ex[8];
#pragma unroll
        for (int h = 0; h < 8; h++) {
            float v = a[h] > 0.f ? a[h] : NEG * a[h];
            ex[h] = expf(v);
            sum[h] += ex[h];
        }
        *(float4*)&exb[(size_t)e * 8]     = make_float4(ex[0], ex[1], ex[2], ex[3]);
        *(float4*)&exb[(size_t)e * 8 + 4] = make_float4(ex[4], ex[5], ex[6], ex[7]);
    }
#pragma unroll
    for (int h = 0; h < 8; h++)
#pragma unroll
        for (int o = 16; o > 0; o >>= 1)
            sum[h] += __shfl_xor_sync(0xffffffffu, sum[h], o);

    int myh = lane >> 2;
    float myr = 1.f / (sum[myh] + 1e-16f);

    // phase 2: gather; dual accumulators + unrolled pairs for MLP
    float ax0 = 0.f, ay0 = 0.f, ax1 = 0.f, ay1 = 0.f;
    int e = 0;
#pragma unroll 4
    for (; e + 1 < deg; e += 2) {
        int s0 = __ldg(&nbr[e]);
        int s1 = __ldg(&nbr[e + 1]);
        float w0 = __ldg(&exb[(size_t)e * 8 + myh]);
        float w1 = __ldg(&exb[(size_t)(e + 1) * 8 + myh]);
        float2 h0 = __ldg((const float2*)&g_Hfull[(size_t)s0 * D1 + 2 * lane]);
        float2 h1 = __ldg((const float2*)&g_Hfull[(size_t)s1 * D1 + 2 * lane]);
        ax0 = fmaf(w0, h0.x, ax0); ay0 = fmaf(w0, h0.y, ay0);
        ax1 = fmaf(w1, h1.x, ax1); ay1 = fmaf(w1, h1.y, ay1);
    }
    if (e < deg) {
        int s0 = __ldg(&nbr[e]);
        float w0 = __ldg(&exb[(size_t)e * 8 + myh]);
        float2 h0 = __ldg((const float2*)&g_Hfull[(size_t)s0 * D1 + 2 * lane]);
        ax0 = fmaf(w0, h0.x, ax0); ay0 = fmaf(w0, h0.y, ay0);
    }
    float ax = (ax0 + ax1) * myr, ay = (ay0 + ay1) * myr;
    float bx = __ldg(&b1[2 * lane]), by = __ldg(&b1[2 * lane + 1]);
    float vx = ax + bx; vx = vx > 0.f ? vx : expm1f(vx);
    float vy = ay + by; vy = vy > 0.f ? vy : expm1f(vy);
    *(float2*)&g_out1[node * D1 + 2 * lane] = make_float2(vx, vy);
}

// ================= layer 2 =================
__global__ void k_gemm2(const float* __restrict__ W2) {
    __shared__ float Ws[D1 * NCLS];
    for (int i = threadIdx.x; i < D1 * NCLS; i += blockDim.x) Ws[i] = W2[i];
    __syncthreads();
    int t = blockIdx.x * blockDim.x + threadIdx.x;
    if (t >= N1V * NCLS) return;
    int row = t / NCLS, col = t - row * NCLS;
    const float* hr = g_out1 + row * D1;
    float acc = 0.f;
#pragma unroll
    for (int k = 0; k < D1; k++) acc = fmaf(hr[k], Ws[k * NCLS + col], acc);
    g_H2[t] = acc;
}

__global__ void k_att2(const float* __restrict__ a_src, const float* __restrict__ a_dst) {
    int i = blockIdx.x * blockDim.x + threadIdx.x;
    if (i >= N1V) return;
    const float* hp = g_H2 + i * NCLS;
    float as = 0.f;
#pragma unroll
    for (int c = 0; c < NCLS; c++) as += hp[c] * a_src[c];
    g_as2[i] = as;
    if (i < N2V) {
        float ad = 0.f;
#pragma unroll
        for (int c = 0; c < NCLS; c++) ad += hp[c] * a_dst[c];
        g_ad2[i] = ad;
    }
}

__global__ void k_edge2_sum() {
    int e = blockIdx.x * blockDim.x + threadIdx.x;
    if (e >= EL2) return;
    int2 sd = g_e2sd[e];
    float al = g_as2[sd.x] + g_ad2[sd.y];
    al = al > 0.f ? al : NEG * al;
    atomicAdd(&g_s2[sd.y], expf(al));
}

__global__ void k_edge2_agg() {
    int t = blockIdx.x * blockDim.x + threadIdx.x;
    if (t >= EL2 * NCLS) return;
    int e = t / NCLS, c = t - e * NCLS;
    int2 sd = g_e2sd[e];
    float al = g_as2[sd.x] + g_ad2[sd.y];
    al = al > 0.f ? al : NEG * al;
    float w = expf(al) / (g_s2[sd.y] + 1e-16f);
    atomicAdd(&g_out2[sd.y * NCLS + c], g_H2[sd.x * NCLS + c] * w);
}

__global__ void k_final(float* __restrict__ out, const float* __restrict__ b2) {
    int d = blockIdx.x;
    int lane = threadIdx.x;
    float v0 = (lane < NCLS) ? g_out2[d * NCLS + lane] + b2[lane] : -INFINITY;
    float v1 = (lane + 32 < NCLS) ? g_out2[d * NCLS + lane + 32] + b2[lane + 32] : -INFINITY;
    float m = fmaxf(v0, v1);
#pragma unroll
    for (int o = 16; o > 0; o >>= 1) m = fmaxf(m, __shfl_xor_sync(0xffffffffu, m, o));
    float s = ((lane < NCLS) ? expf(v0 - m) : 0.f) + ((lane + 32 < NCLS) ? expf(v1 - m) : 0.f);
#pragma unroll
    for (int o = 16; o > 0; o >>= 1) s += __shfl_xor_sync(0xffffffffu, s, o);
    float ls = m + logf(s);
    if (lane < NCLS) out[d * NCLS + lane] = v0 - ls;
    if (lane + 32 < NCLS) out[d * NCLS + lane + 32] = v1 - ls;
}

// ---------------- launch (fork-join: prep overlaps GEMM1) ----------------
extern "C" void kernel_launch(void* const* d_in, const int* in_sizes, int n_in,
                              void* d_out, int out_size) {
    const float* x = nullptr;
    const void* e1 = nullptr;
    const void* e2 = nullptr;
    const float *W1 = nullptr, *as1 = nullptr, *ad1 = nullptr, *b1 = nullptr;
    const float *W2 = nullptr, *as2 = nullptr, *ad2 = nullptr, *b2 = nullptr;

    for (int i = 0; i < n_in; i++) {
        switch (in_sizes[i]) {
            case N0 * F_IN:   x  = (const float*)d_in[i]; break;
            case 2 * E1N:     e1 = d_in[i]; break;
            case 2 * E2N:     e2 = d_in[i]; break;
            case F_IN * D1:
                W1  = (const float*)d_in[i];
                if (i + 3 < n_in) {
                    as1 = (const float*)d_in[i + 1];
                    ad1 = (const float*)d_in[i + 2];
                    b1  = (const float*)d_in[i + 3];
                }
                break;
            case D1 * NCLS:
                W2  = (const float*)d_in[i];
                if (i + 3 < n_in) {
                    as2 = (const float*)d_in[i + 1];
                    ad2 = (const float*)d_in[i + 2];
                    b2  = (const float*)d_in[i + 3];
                }
                break;
            default: break;
        }
    }

    float* out = (float*)d_out;
    const int TPB = 256;

    static cudaStream_t side = nullptr;
    static cudaEvent_t evF = nullptr, evJ = nullptr;
    static int inited = 0;
    if (!inited) {
        cudaStreamCreateWithFlags(&side, cudaStreamNonBlocking);
        cudaEventCreateWithFlags(&evF, cudaEventDisableTiming);
        cudaEventCreateWithFlags(&evJ, cudaEventDisableTiming);
        cudaFuncSetAttribute(k_gemm1_mma, cudaFuncAttributeMaxDynamicSharedMemorySize, SMEM_G1);
        inited = 1;
    }

    // fork: side stream does zero + prep while main stream runs GEMM1
    cudaEventRecord(evF, 0);
    cudaStreamWaitEvent(side, evF, 0);
    k_zero<<<(N2V * NCLS + TPB - 1) / TPB, TPB, 0, side>>>();
    k_prep<<<512, TPB, 0, side>>>(W1, e1, e2);
    cudaEventRecord(evJ, side);

    k_gemm1_mma<<<(N0 + 127) / 128, TPB, SMEM_G1>>>(x, as1, ad1);

    // join
    cudaStreamWaitEvent(0, evJ, 0);
    k_edge1_fused<<<(N1V * 32 + TPB - 1) / TPB, TPB>>>(b1);
    k_gemm2<<<(N1V * NCLS + TPB - 1) / TPB, TPB>>>(W2);
    k_att2<<<(N1V + TPB - 1) / TPB, TPB>>>(as2, ad2);
    k_edge2_sum<<<(EL2 + TPB - 1) / TPB, TPB>>>();
    k_edge2_agg<<<(EL2 * NCLS + TPB - 1) / TPB, TPB>>>();
    k_final<<<N2V, 32>>>(out, b2);
}

// round 16
// speedup vs baseline: 1.2984x; 1.0051x over previous
#include <cuda_runtime.h>
#include <cuda_bf16.h>
#include <cuda_fp16.h>
#include <math.h>

#define N0   120000
#define N1V  12000
#define N2V  1024
#define E1N  300000
#define E2N  10240
#define F_IN 602
#define H1N  8
#define C1N  8
#define D1   64
#define NCLS 41
#define NEG  0.2f

#define EL1  (E1N + N1V)   // 312000
#define EL2  (E2N + N2V)   // 11264
#define KPAD 608
#define CAP  128

// ---------------- scratch ----------------
__device__ float          g_Hfull[(size_t)N0 * D1];
__device__ float          g_as1[N0 * H1N];
__device__ float          g_ad1[N1V * H1N];
__device__ float          g_ex1[(size_t)N1V * CAP * H1N];
__device__ float          g_out1[N1V * D1];
__device__ float          g_H2[N1V * NCLS];
__device__ float          g_as2[N1V];
__device__ float          g_ad2[N2V];
__device__ float          g_s2[N2V];
__device__ float          g_out2[N2V * NCLS];
__device__ __half         g_W1h[D1 * KPAD];
__device__ int2           g_e2sd[EL2];
__device__ int            g_cnt1[N1V];
__device__ int            g_nbr1[N1V * CAP];

// ================= zero (side stream) =================
__global__ void k_zero() {
    int i = blockIdx.x * blockDim.x + threadIdx.x;
    if (i < N1V) g_cnt1[i] = 0;
    if (i < N2V * NCLS) g_out2[i] = 0.f;
    if (i < N2V) g_s2[i] = 0.f;
}

// ================= edge decode + bucket scatter (side stream, ∥ GEMM1) =================
__global__ void k_prep_e(const void* e1, const void* e2) {
    __shared__ int se64;
    if (threadIdx.x == 0) {
        const long long* p = (const long long*)e1;
        bool ok = true;
        for (int i = 0; i < 16; i++) {
            long long v = p[i];
            if (v < 0 || v >= (long long)N0) { ok = false; break; }
        }
        se64 = ok ? 1 : 0;
    }
    __syncthreads();
    int e64 = se64;
    int nt = gridDim.x * blockDim.x;
    int t0 = blockIdx.x * blockDim.x + threadIdx.x;

    for (int e = t0; e < EL1; e += nt) {
        int s, d;
        if (e < E1N) {
            if (e64) {
                s = (int)((const long long*)e1)[e];
                d = (int)((const long long*)e1)[E1N + e];
            } else {
                s = ((const int*)e1)[e];
                d = ((const int*)e1)[E1N + e];
            }
        } else { s = d = e - E1N; }
        int pos = atomicAdd(&g_cnt1[d], 1);
        if (pos < CAP) g_nbr1[d * CAP + pos] = s;
    }
    for (int e = t0; e < EL2; e += nt) {
        int s, d;
        if (e < E2N) {
            if (e64) {
                s = (int)((const long long*)e2)[e];
                d = (int)((const long long*)e2)[E2N + e];
            } else {
                s = ((const int*)e2)[e];
                d = ((const int*)e2)[E2N + e];
            }
        } else { s = d = e - E2N; }
        g_e2sd[e] = make_int2(s, d);
    }
}

// ================= W1 -> fp16 (MAIN stream, before GEMM1: fixes R14 race) =================
__global__ void k_prep_w(const float* __restrict__ W1) {
    int nt = gridDim.x * blockDim.x;
    for (int i = blockIdx.x * blockDim.x + threadIdx.x; i < D1 * KPAD; i += nt) {
        int n = i / KPAD, k = i - n * KPAD;
        float v = (k < F_IN) ? W1[(size_t)k * D1 + n] : 0.f;
        g_W1h[i] = __float2half_rn(v);
    }
}

// ================= GEMM1 — pure fp16, hoisted A addressing (unchanged) =================
#define KC      32
#define NCHUNK  19
#define SA_U32  20
#define SRB     80
#define OFF_AH  0
#define OFF_BH  10240
#define BUFB    15360
#define SMEM_G1 36864
#define CS_STRIDE 72
#define AROWS   (16 * F_IN)

__device__ __forceinline__ unsigned smem_u32(const void* p) {
    unsigned a;
    asm("{ .reg .u64 t; cvta.to.shared.u64 t, %1; cvt.u32.u64 %0, t; }" : "=r"(a) : "l"(p));
    return a;
}

__device__ __forceinline__ unsigned cvt2h1(float2 v) {
    __half2 h = __float22half2_rn(v);
    return *(unsigned*)&h;
}

__device__ __forceinline__ void mma_f16(float* c, const unsigned* a, unsigned b0, unsigned b1) {
    asm volatile(
        "mma.sync.aligned.m16n8k16.row.col.f32.f16.f16.f32 "
        "{%0,%1,%2,%3}, {%4,%5,%6,%7}, {%8,%9}, {%0,%1,%2,%3};"
        : "+f"(c[0]), "+f"(c[1]), "+f"(c[2]), "+f"(c[3])
        : "r"(a[0]), "r"(a[1]), "r"(a[2]), "r"(a[3]), "r"(b0), "r"(b1));
}

__device__ __forceinline__ void ldm4(unsigned addr, unsigned* r) {
    asm volatile("ldmatrix.sync.aligned.m8n8.x4.shared.b16 {%0,%1,%2,%3}, [%4];"
                 : "=r"(r[0]), "=r"(r[1]), "=r"(r[2]), "=r"(r[3]) : "r"(addr));
}

__device__ __forceinline__ void cpa16(unsigned dst, const void* src) {
    asm volatile("cp.async.cg.shared.global [%0], [%1], 16;" :: "r"(dst), "l"(src));
}

__global__ void __launch_bounds__(256, 3)
k_gemm1_mma(const float* __restrict__ x,
            const float* __restrict__ a_src, const float* __restrict__ a_dst) {
    extern __shared__ unsigned char smem[];
    unsigned sb = smem_u32(smem);
    int t = threadIdx.x;
    int w = t >> 5, lane = t & 31;
    int g = lane >> 2, tig = lane & 3;
    int wm = w & 3, wn = w >> 2;
    int row0 = blockIdx.x * 128;

    float acc[2][4][4];
#pragma unroll
    for (int mi = 0; mi < 2; mi++)
#pragma unroll
        for (int ni = 0; ni < 4; ni++)
#pragma unroll
            for (int q = 0; q < 4; q++) acc[mi][ni][q] = 0.f;

    int r0  = t >> 4;
    int kq2 = (t & 15) * 2;
    const float* aptr = x + (size_t)(row0 + r0) * F_IN + kq2;
    unsigned amask = 0;
#pragma unroll
    for (int j = 0; j < 8; j++)
        if (row0 + r0 + 16 * j < N0) amask |= 1u << j;
    unsigned a_soff = (unsigned)(r0 * SA_U32 + (t & 15)) * 4;

    int bn = t >> 2, bq = t & 3;
    unsigned bdst_off = (unsigned)(bn * SRB + bq * 16);
    int bsrc_elem = bn * KPAD + bq * 8;

    int arow = ((lane >> 3) & 1) * 8 + (lane & 7);
    unsigned a_loff = (unsigned)((wm * 32 + arow) * SRB + (lane >> 4) * 16);
    int brow = ((lane >> 4) << 3) + (lane & 7);
    unsigned b_loff = (unsigned)((wn * 32 + brow) * SRB + ((lane >> 3) & 1) * 16);

    {
        unsigned* Ah = (unsigned*)(smem + OFF_AH + a_soff);
#pragma unroll
        for (int j = 0; j < 8; j++) {
            float2 v = (amask >> j) & 1 ? *(const float2*)(aptr + j * AROWS)
                                        : make_float2(0.f, 0.f);
            Ah[j * (16 * SA_U32)] = cvt2h1(v);
        }
        cpa16(sb + OFF_BH + bdst_off, (const void*)(g_W1h + bsrc_elem));
        asm volatile("cp.async.commit_group;");
        asm volatile("cp.async.wait_group 0;");
    }
    __syncthreads();

    for (int c = 0; c < NCHUNK; c++) {
        int cur = c & 1, nxt = cur ^ 1;
        bool have_next = (c + 1 < NCHUNK);
        float2 av[8];
        if (have_next) {
            int koff = (c + 1) * KC;
            cpa16(sb + nxt * BUFB + OFF_BH + bdst_off, (const void*)(g_W1h + bsrc_elem + koff));
            asm volatile("cp.async.commit_group;");
            bool colok = (koff + kq2 + 1 < F_IN);
            const float* ap = aptr + koff;
#pragma unroll
            for (int j = 0; j < 8; j++)
                av[j] = (colok && ((amask >> j) & 1)) ? *(const float2*)(ap + j * AROWS)
                                                      : make_float2(0.f, 0.f);
        }
        {
            unsigned abh = sb + cur * BUFB + OFF_AH + a_loff;
            unsigned bbh = sb + cur * BUFB + OFF_BH + b_loff;
#pragma unroll
            for (int kb = 0; kb < 2; kb++) {
                unsigned ko = kb * 32;
                unsigned ah[2][4], bh[2][4];
#pragma unroll
                for (int mi = 0; mi < 2; mi++)
                    ldm4(abh + mi * (16 * SRB) + ko, ah[mi]);
#pragma unroll
                for (int nb = 0; nb < 2; nb++)
                    ldm4(bbh + nb * (16 * SRB) + ko, bh[nb]);
#pragma unroll
                for (int mi = 0; mi < 2; mi++)
#pragma unroll
                    for (int nb = 0; nb < 2; nb++) {
                        mma_f16(acc[mi][nb * 2 + 0], ah[mi], bh[nb][0], bh[nb][1]);
                        mma_f16(acc[mi][nb * 2 + 1], ah[mi], bh[nb][2], bh[nb][3]);
                    }
            }
        }
        if (have_next) {
            unsigned* Ah = (unsigned*)(smem + nxt * BUFB + OFF_AH + a_soff);
#pragma unroll
            for (int j = 0; j < 8; j++)
                Ah[j * (16 * SA_U32)] = cvt2h1(av[j]);
        }
        asm volatile("cp.async.wait_group 0;");
        __syncthreads();
    }

    float* Cs = (float*)smem;
#pragma unroll
    for (int mi = 0; mi < 2; mi++)
#pragma unroll
        for (int ni = 0; ni < 4; ni++) {
            int r = wm * 32 + mi * 16 + g;
            int cc = wn * 32 + ni * 8 + tig * 2;
            Cs[r * CS_STRIDE + cc]           = acc[mi][ni][0];
            Cs[r * CS_STRIDE + cc + 1]       = acc[mi][ni][1];
            Cs[(r + 8) * CS_STRIDE + cc]     = acc[mi][ni][2];
            Cs[(r + 8) * CS_STRIDE + cc + 1] = acc[mi][ni][3];
        }
    __syncthreads();

#pragma unroll
    for (int it = 0; it < 8; it++) {
        int r = (t >> 4) + 16 * it;
        int c4 = (t & 15) * 4;
        if (row0 + r < N0) {
            float4 v = *(const float4*)(Cs + r * CS_STRIDE + c4);
            *(float4*)(g_Hfull + (size_t)(row0 + r) * D1 + c4) = v;
        }
    }
    if (t < 128) {
        int m = row0 + t;
        if (m < N0) {
            const float* rr = Cs + t * CS_STRIDE;
#pragma unroll
            for (int h = 0; h < H1N; h++) {
                float as = 0.f, ad = 0.f;
#pragma unroll
                for (int cc = 0; cc < C1N; cc++) {
                    float v = rr[h * C1N + cc];
                    as = fmaf(v, __ldg(&a_src[h * C1N + cc]), as);
                    ad = fmaf(v, __ldg(&a_dst[h * C1N + cc]), ad);
                }
                g_as1[m * H1N + h] = as;
                if (m < N1V) g_ad1[m * H1N + h] = ad;
            }
        }
    }
}

// ================= fused layer-1 softmax + aggregate (smem nbr only, global ex) =================
__global__ void __launch_bounds__(256)
k_edge1_fused(const float* __restrict__ b1) {
    __shared__ int s_nbr[8][CAP];       // 4 KB/CTA: breaks the nbr->Hfull pointer chase
    int wid = threadIdx.x >> 5, lane = threadIdx.x & 31;
    int node = blockIdx.x * 8 + wid;
    if (node >= N1V) return;
    int deg = g_cnt1[node];
    if (deg > CAP) deg = CAP;
    const int* nbr = g_nbr1 + node * CAP;
    int* nbs = s_nbr[wid];
    float* exb = g_ex1 + (size_t)node * CAP * 8;

    float4 adA = __ldg((const float4*)&g_ad1[node * 8]);
    float4 adB = __ldg((const float4*)&g_ad1[node * 8 + 4]);
    float sum[8] = {0.f, 0.f, 0.f, 0.f, 0.f, 0.f, 0.f, 0.f};

    for (int e = lane; e < deg; e += 32) {
        int s = __ldg(&nbr[e]);
        nbs[e] = s;
        float4 sa = __ldg((const float4*)&g_as1[s * 8]);
        float4 sbv = __ldg((const float4*)&g_as1[s * 8 + 4]);
        float a[8] = { sa.x + adA.x, sa.y + adA.y, sa.z + adA.z, sa.w + adA.w,
                       sbv.x + adB.x, sbv.y + adB.y, sbv.z + adB.z, sbv.w + adB.w };
        float ex[8];
#pragma unroll
        for (int h = 0; h < 8; h++) {
            float v = a[h] > 0.f ? a[h] : NEG * a[h];
            ex[h] = expf(v);
            sum[h] += ex[h];
        }
        *(float4*)&exb[(size_t)e * 8]     = make_float4(ex[0], ex[1], ex[2], ex[3]);
        *(float4*)&exb[(size_t)e * 8 + 4] = make_float4(ex[4], ex[5], ex[6], ex[7]);
    }
    __syncwarp();
#pragma unroll
    for (int h = 0; h < 8; h++)
#pragma unroll
        for (int o = 16; o > 0; o >>= 1)
            sum[h] += __shfl_xor_sync(0xffffffffu, sum[h], o);

    int myh = lane >> 2;
    float myr = 1.f / (sum[myh] + 1e-16f);

    float ax0 = 0.f, ay0 = 0.f, ax1 = 0.f, ay1 = 0.f;
    int e = 0;
#pragma unroll 4
    for (; e + 1 < deg; e += 2) {
        int s0 = nbs[e];
        int s1 = nbs[e + 1];
        float w0 = __ldg(&exb[(size_t)e * 8 + myh]);
        float w1 = __ldg(&exb[(size_t)(e + 1) * 8 + myh]);
        float2 h0 = __ldg((const float2*)&g_Hfull[(size_t)s0 * D1 + 2 * lane]);
        float2 h1 = __ldg((const float2*)&g_Hfull[(size_t)s1 * D1 + 2 * lane]);
        ax0 = fmaf(w0, h0.x, ax0); ay0 = fmaf(w0, h0.y, ay0);
        ax1 = fmaf(w1, h1.x, ax1); ay1 = fmaf(w1, h1.y, ay1);
    }
    if (e < deg) {
        int s0 = nbs[e];
        float w0 = __ldg(&exb[(size_t)e * 8 + myh]);
        float2 h0 = __ldg((const float2*)&g_Hfull[(size_t)s0 * D1 + 2 * lane]);
        ax0 = fmaf(w0, h0.x, ax0); ay0 = fmaf(w0, h0.y, ay0);
    }
    float ax = (ax0 + ax1) * myr, ay = (ay0 + ay1) * myr;
    float bx = __ldg(&b1[2 * lane]), by = __ldg(&b1[2 * lane + 1]);
    float vx = ax + bx; vx = vx > 0.f ? vx : expm1f(vx);
    float vy = ay + by; vy = vy > 0.f ? vy : expm1f(vy);
    *(float2*)&g_out1[node * D1 + 2 * lane] = make_float2(vx, vy);
}

// ================= layer 2 =================
__global__ void k_gemm2(const float* __restrict__ W2) {
    __shared__ float Ws[D1 * NCLS];
    for (int i = threadIdx.x; i < D1 * NCLS; i += blockDim.x) Ws[i] = W2[i];
    __syncthreads();
    int t = blockIdx.x * blockDim.x + threadIdx.x;
    if (t >= N1V * NCLS) return;
    int row = t / NCLS, col = t - row * NCLS;
    const float* hr = g_out1 + row * D1;
    float acc = 0.f;
#pragma unroll
    for (int k = 0; k < D1; k++) acc = fmaf(hr[k], Ws[k * NCLS + col], acc);
    g_H2[t] = acc;
}

__global__ void k_att2(const float* __restrict__ a_src, const float* __restrict__ a_dst) {
    int i = blockIdx.x * blockDim.x + threadIdx.x;
    if (i >= N1V) return;
    const float* hp = g_H2 + i * NCLS;
    float as = 0.f;
#pragma unroll
    for (int c = 0; c < NCLS; c++) as += hp[c] * a_src[c];
    g_as2[i] = as;
    if (i < N2V) {
        float ad = 0.f;
#pragma unroll
        for (int c = 0; c < NCLS; c++) ad += hp[c] * a_dst[c];
        g_ad2[i] = ad;
    }
}

__global__ void k_edge2_sum() {
    int e = blockIdx.x * blockDim.x + threadIdx.x;
    if (e >= EL2) return;
    int2 sd = g_e2sd[e];
    float al = g_as2[sd.x] + g_ad2[sd.y];
    al = al > 0.f ? al : NEG * al;
    atomicAdd(&g_s2[sd.y], expf(al));
}

__global__ void k_edge2_agg() {
    int t = blockIdx.x * blockDim.x + threadIdx.x;
    if (t >= EL2 * NCLS) return;
    int e = t / NCLS, c = t - e * NCLS;
    int2 sd = g_e2sd[e];
    float al = g_as2[sd.x] + g_ad2[sd.y];
    al = al > 0.f ? al : NEG * al;
    float w = expf(al) / (g_s2[sd.y] + 1e-16f);
    atomicAdd(&g_out2[sd.y * NCLS + c], g_H2[sd.x * NCLS + c] * w);
}

__global__ void k_final(float* __restrict__ out, const float* __restrict__ b2) {
    int d = blockIdx.x;
    int lane = threadIdx.x;
    float v0 = (lane < NCLS) ? g_out2[d * NCLS + lane] + b2[lane] : -INFINITY;
    float v1 = (lane + 32 < NCLS) ? g_out2[d * NCLS + lane + 32] + b2[lane + 32] : -INFINITY;
    float m = fmaxf(v0, v1);
#pragma unroll
    for (int o = 16; o > 0; o >>= 1) m = fmaxf(m, __shfl_xor_sync(0xffffffffu, m, o));
    float s = ((lane < NCLS) ? expf(v0 - m) : 0.f) + ((lane + 32 < NCLS) ? expf(v1 - m) : 0.f);
#pragma unroll
    for (int o = 16; o > 0; o >>= 1) s += __shfl_xor_sync(0xffffffffu, s, o);
    float ls = m + logf(s);
    if (lane < NCLS) out[d * NCLS + lane] = v0 - ls;
    if (lane + 32 < NCLS) out[d * NCLS + lane + 32] = v1 - ls;
}

// ---------------- launch (prep_e overlaps GEMM1; prep_w races fixed) ----------------
extern "C" void kernel_launch(void* const* d_in, const int* in_sizes, int n_in,
                              void* d_out, int out_size) {
    const float* x = nullptr;
    const void* e1 = nullptr;
    const void* e2 = nullptr;
    const float *W1 = nullptr, *as1 = nullptr, *ad1 = nullptr, *b1 = nullptr;
    const float *W2 = nullptr, *as2 = nullptr, *ad2 = nullptr, *b2 = nullptr;

    for (int i = 0; i < n_in; i++) {
        switch (in_sizes[i]) {
            case N0 * F_IN:   x  = (const float*)d_in[i]; break;
            case 2 * E1N:     e1 = d_in[i]; break;
            case 2 * E2N:     e2 = d_in[i]; break;
            case F_IN * D1:
                W1  = (const float*)d_in[i];
                if (i + 3 < n_in) {
                    as1 = (const float*)d_in[i + 1];
                    ad1 = (const float*)d_in[i + 2];
                    b1  = (const float*)d_in[i + 3];
                }
                break;
            case D1 * NCLS:
                W2  = (const float*)d_in[i];
                if (i + 3 < n_in) {
                    as2 = (const float*)d_in[i + 1];
                    ad2 = (const float*)d_in[i + 2];
                    b2  = (const float*)d_in[i + 3];
                }
                break;
            default: break;
        }
    }

    float* out = (float*)d_out;
    const int TPB = 256;

    static cudaStream_t side = nullptr;
    static cudaEvent_t evF = nullptr, evJ = nullptr;
    static int inited = 0;
    if (!inited) {
        cudaStreamCreateWithFlags(&side, cudaStreamNonBlocking);
        cudaEventCreateWithFlags(&evF, cudaEventDisableTiming);
        cudaEventCreateWithFlags(&evJ, cudaEventDisableTiming);
        cudaFuncSetAttribute(k_gemm1_mma, cudaFuncAttributeMaxDynamicSharedMemorySize, SMEM_G1);
        inited = 1;
    }

    // fork: side does zero + edge prep (independent of GEMM1's data)
    cudaEventRecord(evF, 0);
    cudaStreamWaitEvent(side, evF, 0);
    k_zero<<<(N2V * NCLS + TPB - 1) / TPB, TPB, 0, side>>>();        // 1
    k_prep_e<<<512, TPB, 0, side>>>(e1, e2);                          // 2
    cudaEventRecord(evJ, side);

    // main: W1 conversion MUST precede GEMM1 (fixes R14 race)
    k_prep_w<<<160, TPB>>>(W1);                                       // 3
    k_gemm1_mma<<<(N0 + 127) / 128, TPB, SMEM_G1>>>(x, as1, ad1);     // 4 <- profiled

    // join
    cudaStreamWaitEvent(0, evJ, 0);
    k_edge1_fused<<<(N1V + 7) / 8, TPB>>>(b1);                        // 5
    k_gemm2<<<(N1V * NCLS + TPB - 1) / TPB, TPB>>>(W2);               // 6
    k_att2<<<(N1V + TPB - 1) / TPB, TPB>>>(as2, ad2);                 // 7
    k_edge2_sum<<<(EL2 + TPB - 1) / TPB, TPB>>>();                    // 8
    k_edge2_agg<<<(EL2 * NCLS + TPB - 1) / TPB, TPB>>>();             // 9
    k_final<<<N2V, 32>>>(out, b2);                                    // 10
}

// round 17
// speedup vs baseline: 1.3892x; 1.0699x over previous
#include <cuda_runtime.h>
#include <cuda_bf16.h>
#include <cuda_fp16.h>
#include <math.h>

#define N0   120000
#define N1V  12000
#define N2V  1024
#define E1N  300000
#define E2N  10240
#define F_IN 602
#define H1N  8
#define C1N  8
#define D1   64
#define NCLS 41
#define NEG  0.2f

#define EL1  (E1N + N1V)   // 312000
#define EL2  (E2N + N2V)   // 11264
#define KPAD 608
#define CAP  128
#define CAP2 64            // layer-2 bucket capacity (Poisson(10) tail ~1e-30)

// ---------------- scratch ----------------
__device__ float          g_Hfull[(size_t)N0 * D1];
__device__ float          g_as1[N0 * H1N];
__device__ float          g_ad1[N1V * H1N];
__device__ float          g_ex1[(size_t)N1V * CAP * H1N];
__device__ float          g_out1[N1V * D1];
__device__ float          g_H2[N1V * NCLS];
__device__ float          g_as2[N1V];
__device__ float          g_ad2[N2V];
__device__ __half         g_W1h[D1 * KPAD];
__device__ int            g_cnt1[N1V];
__device__ int            g_nbr1[N1V * CAP];
__device__ int            g_cnt2[N2V];
__device__ int            g_nbr2[N2V * CAP2];

// ================= zero (side stream) =================
__global__ void k_zero() {
    int i = blockIdx.x * blockDim.x + threadIdx.x;
    if (i < N1V) g_cnt1[i] = 0;
    if (i < N2V) g_cnt2[i] = 0;
}

// ================= edge decode + bucket scatter (side stream, ∥ GEMM1) =================
__global__ void k_prep_e(const void* e1, const void* e2) {
    __shared__ int se64;
    if (threadIdx.x == 0) {
        const long long* p = (const long long*)e1;
        bool ok = true;
        for (int i = 0; i < 16; i++) {
            long long v = p[i];
            if (v < 0 || v >= (long long)N0) { ok = false; break; }
        }
        se64 = ok ? 1 : 0;
    }
    __syncthreads();
    int e64 = se64;
    int nt = gridDim.x * blockDim.x;
    int t0 = blockIdx.x * blockDim.x + threadIdx.x;

    for (int e = t0; e < EL1; e += nt) {
        int s, d;
        if (e < E1N) {
            if (e64) {
                s = (int)((const long long*)e1)[e];
                d = (int)((const long long*)e1)[E1N + e];
            } else {
                s = ((const int*)e1)[e];
                d = ((const int*)e1)[E1N + e];
            }
        } else { s = d = e - E1N; }
        int pos = atomicAdd(&g_cnt1[d], 1);
        if (pos < CAP) g_nbr1[d * CAP + pos] = s;
    }
    for (int e = t0; e < EL2; e += nt) {
        int s, d;
        if (e < E2N) {
            if (e64) {
                s = (int)((const long long*)e2)[e];
                d = (int)((const long long*)e2)[E2N + e];
            } else {
                s = ((const int*)e2)[e];
                d = ((const int*)e2)[E2N + e];
            }
        } else { s = d = e - E2N; }
        int pos = atomicAdd(&g_cnt2[d], 1);
        if (pos < CAP2) g_nbr2[d * CAP2 + pos] = s;
    }
}

// ================= W1 -> fp16 (main stream, before GEMM1) =================
__global__ void k_prep_w(const float* __restrict__ W1) {
    int nt = gridDim.x * blockDim.x;
    for (int i = blockIdx.x * blockDim.x + threadIdx.x; i < D1 * KPAD; i += nt) {
        int n = i / KPAD, k = i - n * KPAD;
        float v = (k < F_IN) ? W1[(size_t)k * D1 + n] : 0.f;
        g_W1h[i] = __float2half_rn(v);
    }
}

// ================= GEMM1 — pure fp16, 3-deep A pipeline =================
#define KC      32
#define NCHUNK  19
#define SA_U32  20
#define SRB     80
#define ABUF    10240        // per A buffer (x3): 0, 10240, 20480
#define OFF_B   30720        // B buffers (x2): 30720, 35840
#define SMEM_G1 40960
#define CS_STRIDE 72
#define AROWS   (16 * F_IN)

__device__ __forceinline__ unsigned smem_u32(const void* p) {
    unsigned a;
    asm("{ .reg .u64 t; cvta.to.shared.u64 t, %1; cvt.u32.u64 %0, t; }" : "=r"(a) : "l"(p));
    return a;
}

__device__ __forceinline__ unsigned cvt2h1(float2 v) {
    __half2 h = __float22half2_rn(v);
    return *(unsigned*)&h;
}

__device__ __forceinline__ void mma_f16(float* c, const unsigned* a, unsigned b0, unsigned b1) {
    asm volatile(
        "mma.sync.aligned.m16n8k16.row.col.f32.f16.f16.f32 "
        "{%0,%1,%2,%3}, {%4,%5,%6,%7}, {%8,%9}, {%0,%1,%2,%3};"
        : "+f"(c[0]), "+f"(c[1]), "+f"(c[2]), "+f"(c[3])
        : "r"(a[0]), "r"(a[1]), "r"(a[2]), "r"(a[3]), "r"(b0), "r"(b1));
}

__device__ __forceinline__ void ldm4(unsigned addr, unsigned* r) {
    asm volatile("ldmatrix.sync.aligned.m8n8.x4.shared.b16 {%0,%1,%2,%3}, [%4];"
                 : "=r"(r[0]), "=r"(r[1]), "=r"(r[2]), "=r"(r[3]) : "r"(addr));
}

__device__ __forceinline__ void cpa16(unsigned dst, const void* src) {
    asm volatile("cp.async.cg.shared.global [%0], [%1], 16;" :: "r"(dst), "l"(src));
}

__global__ void __launch_bounds__(256, 3)
k_gemm1_mma(const float* __restrict__ x,
            const float* __restrict__ a_src, const float* __restrict__ a_dst) {
    extern __shared__ unsigned char smem[];
    unsigned sb = smem_u32(smem);
    int t = threadIdx.x;
    int w = t >> 5, lane = t & 31;
    int g = lane >> 2, tig = lane & 3;
    int wm = w & 3, wn = w >> 2;
    int row0 = blockIdx.x * 128;

    float acc[2][4][4];
#pragma unroll
    for (int mi = 0; mi < 2; mi++)
#pragma unroll
        for (int ni = 0; ni < 4; ni++)
#pragma unroll
            for (int q = 0; q < 4; q++) acc[mi][ni][q] = 0.f;

    int r0  = t >> 4;
    int kq2 = (t & 15) * 2;
    const float* aptr = x + (size_t)(row0 + r0) * F_IN + kq2;
    unsigned amask = 0;
#pragma unroll
    for (int j = 0; j < 8; j++)
        if (row0 + r0 + 16 * j < N0) amask |= 1u << j;
    unsigned a_soff = (unsigned)(r0 * SA_U32 + (t & 15)) * 4;

    int bn = t >> 2, bq = t & 3;
    unsigned bdst_off = (unsigned)(bn * SRB + bq * 16);
    int bsrc_elem = bn * KPAD + bq * 8;

    int arow = ((lane >> 3) & 1) * 8 + (lane & 7);
    unsigned a_loff = (unsigned)((wm * 32 + arow) * SRB + (lane >> 4) * 16);
    int brow = ((lane >> 4) << 3) + (lane & 7);
    unsigned b_loff = (unsigned)((wn * 32 + brow) * SRB + ((lane >> 3) & 1) * 16);

    float2 av[8];
    // -------- prologue: chunk 0 direct to A0; B0; issue av loads for chunk 1 --------
    {
        unsigned* Ah = (unsigned*)(smem + a_soff);
#pragma unroll
        for (int j = 0; j < 8; j++) {
            float2 v = (amask >> j) & 1 ? *(const float2*)(aptr + j * AROWS)
                                        : make_float2(0.f, 0.f);
            Ah[j * (16 * SA_U32)] = cvt2h1(v);
        }
        cpa16(sb + OFF_B + bdst_off, (const void*)(g_W1h + bsrc_elem));
        asm volatile("cp.async.commit_group;");
        const float* ap = aptr + KC;
#pragma unroll
        for (int j = 0; j < 8; j++)
            av[j] = (amask >> j) & 1 ? *(const float2*)(ap + j * AROWS)
                                     : make_float2(0.f, 0.f);
        asm volatile("cp.async.wait_group 0;");
    }
    __syncthreads();

    for (int c = 0; c < NCHUNK; c++) {
        int cura = c % 3;
        int curb = c & 1;
        bool have1 = (c + 1 < NCHUNK);
        bool have2 = (c + 2 < NCHUNK);
        // top: store av (chunk c+1) into A[(c+1)%3]; issue B(c+1)
        if (have1) {
            int nxta = cura + 1; if (nxta == 3) nxta = 0;
            unsigned* Ah = (unsigned*)(smem + nxta * ABUF + a_soff);
#pragma unroll
            for (int j = 0; j < 8; j++)
                Ah[j * (16 * SA_U32)] = cvt2h1(av[j]);
            cpa16(sb + OFF_B + (curb ^ 1) * 5120 + bdst_off,
                  (const void*)(g_W1h + bsrc_elem + (c + 1) * KC));
        }
        asm volatile("cp.async.commit_group;");
        // issue av loads for chunk c+2 (full iteration to land)
        if (have2) {
            int koff = (c + 2) * KC;
            bool colok = (koff + kq2 + 1 < F_IN);
            const float* ap = aptr + koff;
#pragma unroll
            for (int j = 0; j < 8; j++)
                av[j] = (colok && ((amask >> j) & 1)) ? *(const float2*)(ap + j * AROWS)
                                                      : make_float2(0.f, 0.f);
        }
        // compute on A[c%3], B[c&1]
        {
            unsigned abh = sb + cura * ABUF + a_loff;
            unsigned bbh = sb + OFF_B + curb * 5120 + b_loff;
#pragma unroll
            for (int kb = 0; kb < 2; kb++) {
                unsigned ko = kb * 32;
                unsigned ah[2][4], bh[2][4];
#pragma unroll
                for (int mi = 0; mi < 2; mi++)
                    ldm4(abh + mi * (16 * SRB) + ko, ah[mi]);
#pragma unroll
                for (int nb = 0; nb < 2; nb++)
                    ldm4(bbh + nb * (16 * SRB) + ko, bh[nb]);
#pragma unroll
                for (int mi = 0; mi < 2; mi++)
#pragma unroll
                    for (int nb = 0; nb < 2; nb++) {
                        mma_f16(acc[mi][nb * 2 + 0], ah[mi], bh[nb][0], bh[nb][1]);
                        mma_f16(acc[mi][nb * 2 + 1], ah[mi], bh[nb][2], bh[nb][3]);
                    }
            }
        }
        asm volatile("cp.async.wait_group 0;");
        __syncthreads();
    }

    // -------- epilogue --------
    float* Cs = (float*)smem;
#pragma unroll
    for (int mi = 0; mi < 2; mi++)
#pragma unroll
        for (int ni = 0; ni < 4; ni++) {
            int r = wm * 32 + mi * 16 + g;
            int cc = wn * 32 + ni * 8 + tig * 2;
            Cs[r * CS_STRIDE + cc]           = acc[mi][ni][0];
            Cs[r * CS_STRIDE + cc + 1]       = acc[mi][ni][1];
            Cs[(r + 8) * CS_STRIDE + cc]     = acc[mi][ni][2];
            Cs[(r + 8) * CS_STRIDE + cc + 1] = acc[mi][ni][3];
        }
    __syncthreads();

#pragma unroll
    for (int it = 0; it < 8; it++) {
        int r = (t >> 4) + 16 * it;
        int c4 = (t & 15) * 4;
        if (row0 + r < N0) {
            float4 v = *(const float4*)(Cs + r * CS_STRIDE + c4);
            *(float4*)(g_Hfull + (size_t)(row0 + r) * D1 + c4) = v;
        }
    }
    if (t < 128) {
        int m = row0 + t;
        if (m < N0) {
            const float* rr = Cs + t * CS_STRIDE;
#pragma unroll
            for (int h = 0; h < H1N; h++) {
                float as = 0.f, ad = 0.f;
#pragma unroll
                for (int cc = 0; cc < C1N; cc++) {
                    float v = rr[h * C1N + cc];
                    as = fmaf(v, __ldg(&a_src[h * C1N + cc]), as);
                    ad = fmaf(v, __ldg(&a_dst[h * C1N + cc]), ad);
                }
                g_as1[m * H1N + h] = as;
                if (m < N1V) g_ad1[m * H1N + h] = ad;
            }
        }
    }
}

// ================= fused layer-1 softmax + aggregate (unchanged) =================
__global__ void __launch_bounds__(256)
k_edge1_fused(const float* __restrict__ b1) {
    __shared__ int s_nbr[8][CAP];
    int wid = threadIdx.x >> 5, lane = threadIdx.x & 31;
    int node = blockIdx.x * 8 + wid;
    if (node >= N1V) return;
    int deg = g_cnt1[node];
    if (deg > CAP) deg = CAP;
    const int* nbr = g_nbr1 + node * CAP;
    int* nbs = s_nbr[wid];
    float* exb = g_ex1 + (size_t)node * CAP * 8;

    float4 adA = __ldg((const float4*)&g_ad1[node * 8]);
    float4 adB = __ldg((const float4*)&g_ad1[node * 8 + 4]);
    float sum[8] = {0.f, 0.f, 0.f, 0.f, 0.f, 0.f, 0.f, 0.f};

    for (int e = lane; e < deg; e += 32) {
        int s = __ldg(&nbr[e]);
        nbs[e] = s;
        float4 sa = __ldg((const float4*)&g_as1[s * 8]);
        float4 sbv = __ldg((const float4*)&g_as1[s * 8 + 4]);
        float a[8] = { sa.x + adA.x, sa.y + adA.y, sa.z + adA.z, sa.w + adA.w,
                       sbv.x + adB.x, sbv.y + adB.y, sbv.z + adB.z, sbv.w + adB.w };
        float ex[8];
#pragma unroll
        for (int h = 0; h < 8; h++) {
            float v = a[h] > 0.f ? a[h] : NEG * a[h];
            ex[h] = expf(v);
            sum[h] += ex[h];
        }
        *(float4*)&exb[(size_t)e * 8]     = make_float4(ex[0], ex[1], ex[2], ex[3]);
        *(float4*)&exb[(size_t)e * 8 + 4] = make_float4(ex[4], ex[5], ex[6], ex[7]);
    }
    __syncwarp();
#pragma unroll
    for (int h = 0; h < 8; h++)
#pragma unroll
        for (int o = 16; o > 0; o >>= 1)
            sum[h] += __shfl_xor_sync(0xffffffffu, sum[h], o);

    int myh = lane >> 2;
    float myr = 1.f / (sum[myh] + 1e-16f);

    float ax0 = 0.f, ay0 = 0.f, ax1 = 0.f, ay1 = 0.f;
    int e = 0;
#pragma unroll 4
    for (; e + 1 < deg; e += 2) {
        int s0 = nbs[e];
        int s1 = nbs[e + 1];
        float w0 = __ldg(&exb[(size_t)e * 8 + myh]);
        float w1 = __ldg(&exb[(size_t)(e + 1) * 8 + myh]);
        float2 h0 = __ldg((const float2*)&g_Hfull[(size_t)s0 * D1 + 2 * lane]);
        float2 h1 = __ldg((const float2*)&g_Hfull[(size_t)s1 * D1 + 2 * lane]);
        ax0 = fmaf(w0, h0.x, ax0); ay0 = fmaf(w0, h0.y, ay0);
        ax1 = fmaf(w1, h1.x, ax1); ay1 = fmaf(w1, h1.y, ay1);
    }
    if (e < deg) {
        int s0 = nbs[e];
        float w0 = __ldg(&exb[(size_t)e * 8 + myh]);
        float2 h0 = __ldg((const float2*)&g_Hfull[(size_t)s0 * D1 + 2 * lane]);
        ax0 = fmaf(w0, h0.x, ax0); ay0 = fmaf(w0, h0.y, ay0);
    }
    float ax = (ax0 + ax1) * myr, ay = (ay0 + ay1) * myr;
    float bx = __ldg(&b1[2 * lane]), by = __ldg(&b1[2 * lane + 1]);
    float vx = ax + bx; vx = vx > 0.f ? vx : expm1f(vx);
    float vy = ay + by; vy = vy > 0.f ? vy : expm1f(vy);
    *(float2*)&g_out1[node * D1 + 2 * lane] = make_float2(vx, vy);
}

// ================= layer 2: GEMM + attention logits =================
__global__ void k_gemm2(const float* __restrict__ W2) {
    __shared__ float Ws[D1 * NCLS];
    for (int i = threadIdx.x; i < D1 * NCLS; i += blockDim.x) Ws[i] = W2[i];
    __syncthreads();
    int t = blockIdx.x * blockDim.x + threadIdx.x;
    if (t >= N1V * NCLS) return;
    int row = t / NCLS, col = t - row * NCLS;
    const float* hr = g_out1 + row * D1;
    float acc = 0.f;
#pragma unroll
    for (int k = 0; k < D1; k++) acc = fmaf(hr[k], Ws[k * NCLS + col], acc);
    g_H2[t] = acc;
}

__global__ void k_att2(const float* __restrict__ a_src, const float* __restrict__ a_dst) {
    int i = blockIdx.x * blockDim.x + threadIdx.x;
    if (i >= N1V) return;
    const float* hp = g_H2 + i * NCLS;
    float as = 0.f;
#pragma unroll
    for (int c = 0; c < NCLS; c++) as += hp[c] * a_src[c];
    g_as2[i] = as;
    if (i < N2V) {
        float ad = 0.f;
#pragma unroll
        for (int c = 0; c < NCLS; c++) ad += hp[c] * a_dst[c];
        g_ad2[i] = ad;
    }
}

// ================= fused layer-2 tail: softmax + aggregate + bias + log_softmax =================
__global__ void __launch_bounds__(64)
k_tail(float* __restrict__ out, const float* __restrict__ b2) {
    __shared__ float red[64];
    int d = blockIdx.x;
    int c = threadIdx.x;
    int deg = g_cnt2[d];
    if (deg > CAP2) deg = CAP2;
    const int* nbr = g_nbr2 + d * CAP2;
    float ad = g_ad2[d];

    float num = 0.f, sumw = 0.f;
    for (int e = 0; e < deg; e++) {
        int s = __ldg(&nbr[e]);
        float al = __ldg(&g_as2[s]) + ad;
        al = al > 0.f ? al : NEG * al;
        float wv = expf(al);
        sumw += wv;
        if (c < NCLS) num = fmaf(wv, __ldg(&g_H2[s * NCLS + c]), num);
    }
    float logit = (c < NCLS) ? num / (sumw + 1e-16f) + __ldg(&b2[c]) : -INFINITY;

    red[c] = logit;
    __syncthreads();
#pragma unroll
    for (int o = 32; o > 0; o >>= 1) {
        if (c < o) red[c] = fmaxf(red[c], red[c + o]);
        __syncthreads();
    }
    float m = red[0];
    __syncthreads();
    red[c] = (c < NCLS) ? expf(logit - m) : 0.f;
    __syncthreads();
#pragma unroll
    for (int o = 32; o > 0; o >>= 1) {
        if (c < o) red[c] += red[c + o];
        __syncthreads();
    }
    float ls = m + logf(red[0]);
    if (c < NCLS) out[d * NCLS + c] = logit - ls;
}

// ---------------- launch ----------------
extern "C" void kernel_launch(void* const* d_in, const int* in_sizes, int n_in,
                              void* d_out, int out_size) {
    const float* x = nullptr;
    const void* e1 = nullptr;
    const void* e2 = nullptr;
    const float *W1 = nullptr, *as1 = nullptr, *ad1 = nullptr, *b1 = nullptr;
    const float *W2 = nullptr, *as2 = nullptr, *ad2 = nullptr, *b2 = nullptr;

    for (int i = 0; i < n_in; i++) {
        switch (in_sizes[i]) {
            case N0 * F_IN:   x  = (const float*)d_in[i]; break;
            case 2 * E1N:     e1 = d_in[i]; break;
            case 2 * E2N:     e2 = d_in[i]; break;
            case F_IN * D1:
                W1  = (const float*)d_in[i];
                if (i + 3 < n_in) {
                    as1 = (const float*)d_in[i + 1];
                    ad1 = (const float*)d_in[i + 2];
                    b1  = (const float*)d_in[i + 3];
                }
                break;
            case D1 * NCLS:
                W2  = (const float*)d_in[i];
                if (i + 3 < n_in) {
                    as2 = (const float*)d_in[i + 1];
                    ad2 = (const float*)d_in[i + 2];
                    b2  = (const float*)d_in[i + 3];
                }
                break;
            default: break;
        }
    }

    float* out = (float*)d_out;
    const int TPB = 256;

    static cudaStream_t side = nullptr;
    static cudaEvent_t evF = nullptr, evJ = nullptr;
    static int inited = 0;
    if (!inited) {
        cudaStreamCreateWithFlags(&side, cudaStreamNonBlocking);
        cudaEventCreateWithFlags(&evF, cudaEventDisableTiming);
        cudaEventCreateWithFlags(&evJ, cudaEventDisableTiming);
        cudaFuncSetAttribute(k_gemm1_mma, cudaFuncAttributeMaxDynamicSharedMemorySize, SMEM_G1);
        inited = 1;
    }

    // fork: side does zero + edge prep (independent of GEMM1's data)
    cudaEventRecord(evF, 0);
    cudaStreamWaitEvent(side, evF, 0);
    k_zero<<<(N1V + TPB - 1) / TPB, TPB, 0, side>>>();               // 1
    k_prep_e<<<512, TPB, 0, side>>>(e1, e2);                          // 2
    cudaEventRecord(evJ, side);

    // main
    k_prep_w<<<160, TPB>>>(W1);                                       // 3
    k_gemm1_mma<<<(N0 + 127) / 128, TPB, SMEM_G1>>>(x, as1, ad1);     // 4 <- profiled

    // join
    cudaStreamWaitEvent(0, evJ, 0);
    k_edge1_fused<<<(N1V + 7) / 8, TPB>>>(b1);                        // 5
    k_gemm2<<<(N1V * NCLS + TPB - 1) / TPB, TPB>>>(W2);               // 6
    k_att2<<<(N1V + TPB - 1) / TPB, TPB>>>(as2, ad2);                 // 7
    k_tail<<<N2V, 64>>>(out, b2);                                     // 8
}